// round 12
// baseline (speedup 1.0000x reference)
#include <cuda_runtime.h>
#include <math.h>

#define BATCH   16
#define T       640
#define EMBD    256
#define HEADS   8
#define DHDIM   32
#define BHDIM   128      // BATCH*HEADS
#define NHASH   8
#define NCHUNK  80
#define NROWS   10240    // BATCH*T

// ---------------- scratch (device globals; no allocation allowed) ----------------
__device__ float g_tokens[NROWS*EMBD];
__device__ float g_qk[BHDIM*T*DHDIM];
__device__ float g_v [BHDIM*T*DHDIM];
__device__ int   g_bucket[BHDIM*NHASH*T];
__device__ int   g_sorted[BHDIM*NHASH*T];
__device__ float g_ohash[(size_t)BHDIM*NHASH*T*DHDIM];
__device__ float g_logit[BHDIM*NHASH*T];
__device__ float g_omerged[NROWS*EMBD];
// pre-transposed + pre-split weights: [n][k] layout, hi/lo planes
__device__ float g_wqkT_hi[EMBD*EMBD], g_wqkT_lo[EMBD*EMBD];
__device__ float g_wvT_hi [EMBD*EMBD], g_wvT_lo [EMBD*EMBD];
__device__ float g_woT_hi [EMBD*EMBD], g_woT_lo [EMBD*EMBD];

// ---------------- tf32 mma.sync helpers ----------------
__device__ __forceinline__ void mma_tf32(float* d, const unsigned* a, const unsigned* b){
  asm volatile(
    "mma.sync.aligned.m16n8k8.row.col.f32.tf32.tf32.f32 "
    "{%0,%1,%2,%3}, {%4,%5,%6,%7}, {%8,%9}, {%0,%1,%2,%3};"
    : "+f"(d[0]), "+f"(d[1]), "+f"(d[2]), "+f"(d[3])
    : "r"(a[0]), "r"(a[1]), "r"(a[2]), "r"(a[3]), "r"(b[0]), "r"(b[1]));
}
// cheap split: hi = x with low 13 mantissa bits zeroed (exact tf32 value), lo = x - hi
__device__ __forceinline__ void tf32_split(float x, unsigned &hi, unsigned &lo){
  unsigned hb = __float_as_uint(x) & 0xFFFFE000u;
  hi = hb;
  lo = __float_as_uint(x - __uint_as_float(hb));
}
__device__ __forceinline__ unsigned fu(float x){ return __float_as_uint(x); }
// within-8 k-permutation: (0,4,1,5,2,6,3,7) pairing (tig, tig+4) -> (2tig, 2tig+1)
__device__ __forceinline__ int kperm(int c){
  int w = c & 7;
  return (c & ~7) + ((w & 3) << 1) + ((w >> 2) & 1);
}

// ---------------- cp.async helpers ----------------
__device__ __forceinline__ void cp16(void* dst, const void* src){
  unsigned d = (unsigned)__cvta_generic_to_shared(dst);
  asm volatile("cp.async.ca.shared.global [%0], [%1], 16;" :: "r"(d), "l"(src));
}
#define CP_COMMIT() asm volatile("cp.async.commit_group;" ::: "memory")
#define CP_WAIT1()  asm volatile("cp.async.wait_group 1;" ::: "memory")
#define CP_WAIT0()  asm volatile("cp.async.wait_group 0;" ::: "memory")

// ---------------- stage 0: weight transpose + split ----------------
__global__ void wsplit_kernel(const float* __restrict__ wqk,
                              const float* __restrict__ wv,
                              const float* __restrict__ wo){
  __shared__ float tile[32][33];
  int z = blockIdx.z;
  const float* src = (z==0) ? wqk : (z==1) ? wv : wo;
  float* dh = (z==0) ? g_wqkT_hi : (z==1) ? g_wvT_hi : g_woT_hi;
  float* dl = (z==0) ? g_wqkT_lo : (z==1) ? g_wvT_lo : g_woT_lo;
  int n0 = blockIdx.x*32, k0 = blockIdx.y*32;
  #pragma unroll
  for (int r=0;r<4;r++){
    int k = threadIdx.y + r*8;
    tile[k][threadIdx.x] = src[(k0+k)*EMBD + n0 + threadIdx.x];
  }
  __syncthreads();
  #pragma unroll
  for (int r=0;r<4;r++){
    int n = threadIdx.y + r*8;
    float v = tile[threadIdx.x][n];
    float hv = __uint_as_float(__float_as_uint(v) & 0xFFFFE000u);
    int oi = (n0+n)*EMBD + k0 + threadIdx.x;
    dh[oi] = hv;
    dl[oi] = v - hv;
  }
}

// ---------------- stage 1: maxpool + Haar DWT -> tokens (smem tiled) ----------------
__global__ __launch_bounds__(256) void frontend_kernel(const float* __restrict__ x){
  __shared__ float s_x[32][33];
  int plane = blockIdx.x;            // b*128 + ch
  int b = plane >> 7, ch = plane & 127;
  const float* xp = x + (size_t)plane*1024;
  int t = threadIdx.x;

  {
    float4 v = *(const float4*)(xp + t*4);
    int r = t >> 3, c4 = (t & 7)*4;
    s_x[r][c4]=v.x; s_x[r][c4+1]=v.y; s_x[r][c4+2]=v.z; s_x[r][c4+3]=v.w;
  }
  __syncthreads();

  int i = t >> 4, j = t & 15;
  float m = -INFINITY;
  int r0 = 2*i-1, c0 = 2*j-1;
  #pragma unroll
  for (int dr=0;dr<3;dr++){
    int r = r0+dr; if (r<0 || r>31) continue;
    #pragma unroll
    for (int dc=0;dc<3;dc++){
      int cc = c0+dc; if (cc<0 || cc>31) continue;
      m = fmaxf(m, s_x[r][cc]);
    }
  }
  float a  = s_x[2*i][2*j];
  float bb = s_x[2*i][2*j+1];
  float c  = s_x[2*i+1][2*j];
  float d  = s_x[2*i+1][2*j+1];
  float ll = (a+bb+c+d)*0.5f;
  float lh = (a-bb+c-d)*0.5f;
  float hl = (a+bb-c-d)*0.5f;
  float hh = (a-bb-c+d)*0.5f;

  size_t rowbase = (size_t)b*640;
  g_tokens[(rowbase + ch      )*256 + t] = m;
  g_tokens[(rowbase + 128 + ch)*256 + t] = ll;
  g_tokens[(rowbase + 256 + ch)*256 + t] = lh;
  g_tokens[(rowbase + 384 + ch)*256 + t] = hl;
  g_tokens[(rowbase + 512 + ch)*256 + t] = hh;
}

// ---------------- stage 2: fused qk/v GEMM, 3xTF32, cp.async double-buffered ----------------
#define QKV_TILE (128*36 + 4*64*36)          // 13824 floats per stage
#define SMEM_QKV (2*QKV_TILE*4)              // 110.6 KB

__global__ __launch_bounds__(256) void gemm_qkv_tc(){
  extern __shared__ float sm[];
  int tid = threadIdx.x;
  int m0 = blockIdx.y*128, n0 = blockIdx.x*64;
  int warp = tid>>5, lane = tid&31;
  int g = lane>>2, tig = lane&3;
  int rA = warp*16 + g, rB = rA + 8;

  int lrow = tid>>1, lhalf = (tid&1)*16;
  int lbn  = tid>>2, lkq   = (tid&3)*8;

  float acc1[8][4], acc2[8][4];
  #pragma unroll
  for (int nt=0;nt<8;nt++)
    #pragma unroll
    for (int u=0;u<4;u++){ acc1[nt][u]=0.f; acc2[nt][u]=0.f; }

  auto load_tile = [&](int it, float* base){
    int kc = it*32;
    float* s_a   = base;
    float* s_b1h = base + 128*36;
    float* s_b1l = s_b1h + 64*36;
    float* s_b2h = s_b1l + 64*36;
    float* s_b2l = s_b2h + 64*36;
    const float* asrc = g_tokens + (size_t)(m0+lrow)*EMBD + kc + lhalf;
    cp16(&s_a[lrow*36+lhalf],    asrc);
    cp16(&s_a[lrow*36+lhalf+4],  asrc+4);
    cp16(&s_a[lrow*36+lhalf+8],  asrc+8);
    cp16(&s_a[lrow*36+lhalf+12], asrc+12);
    size_t bo = (size_t)(n0+lbn)*EMBD + kc + lkq;
    cp16(&s_b1h[lbn*36+lkq],   &g_wqkT_hi[bo]);
    cp16(&s_b1h[lbn*36+lkq+4], &g_wqkT_hi[bo+4]);
    cp16(&s_b1l[lbn*36+lkq],   &g_wqkT_lo[bo]);
    cp16(&s_b1l[lbn*36+lkq+4], &g_wqkT_lo[bo+4]);
    cp16(&s_b2h[lbn*36+lkq],   &g_wvT_hi[bo]);
    cp16(&s_b2h[lbn*36+lkq+4], &g_wvT_hi[bo+4]);
    cp16(&s_b2l[lbn*36+lkq],   &g_wvT_lo[bo]);
    cp16(&s_b2l[lbn*36+lkq+4], &g_wvT_lo[bo+4]);
  };

  load_tile(0, sm);
  CP_COMMIT();

  for (int it=0; it<8; it++){
    if (it < 7){
      load_tile(it+1, sm + ((it+1)&1)*QKV_TILE);
      CP_COMMIT();
      CP_WAIT1();
    } else {
      CP_WAIT0();
    }
    __syncthreads();

    float* base  = sm + (it&1)*QKV_TILE;
    float* s_a   = base;
    float* s_b1h = base + 128*36;
    float* s_b1l = s_b1h + 64*36;
    float* s_b2h = s_b1l + 64*36;
    float* s_b2l = s_b2h + 64*36;

    #pragma unroll
    for (int kk=0;kk<32;kk+=8){
      unsigned ah[4], al[4];
      tf32_split(s_a[rA*36+kk+tig],   ah[0], al[0]);
      tf32_split(s_a[rB*36+kk+tig],   ah[1], al[1]);
      tf32_split(s_a[rA*36+kk+tig+4], ah[2], al[2]);
      tf32_split(s_a[rB*36+kk+tig+4], ah[3], al[3]);
      #pragma unroll
      for (int nt=0;nt<8;nt++){
        int nr = nt*8 + g;
        unsigned b1h[2] = { fu(s_b1h[nr*36+kk+tig]), fu(s_b1h[nr*36+kk+tig+4]) };
        unsigned b1l[2] = { fu(s_b1l[nr*36+kk+tig]), fu(s_b1l[nr*36+kk+tig+4]) };
        mma_tf32(acc1[nt], ah, b1h);
        mma_tf32(acc1[nt], al, b1h);
        mma_tf32(acc1[nt], ah, b1l);
        unsigned b2h[2] = { fu(s_b2h[nr*36+kk+tig]), fu(s_b2h[nr*36+kk+tig+4]) };
        unsigned b2l[2] = { fu(s_b2l[nr*36+kk+tig]), fu(s_b2l[nr*36+kk+tig+4]) };
        mma_tf32(acc2[nt], ah, b2h);
        mma_tf32(acc2[nt], al, b2h);
        mma_tf32(acc2[nt], ah, b2l);
      }
    }
    __syncthreads();
  }

  int rowA = m0 + rA, rowB = m0 + rB;
  int bA = rowA/640, tokA = rowA - bA*640;
  int bB = rowB/640, tokB = rowB - bB*640;
  #pragma unroll
  for (int nt=0;nt<8;nt++){
    int col = n0 + nt*8 + 2*tig;
    int head = col>>5, dh = col&31;
    size_t oA = ((size_t)(bA*8+head)*640 + tokA)*32 + dh;
    size_t oB = ((size_t)(bB*8+head)*640 + tokB)*32 + dh;
    *(float2*)&g_qk[oA] = make_float2(acc1[nt][0], acc1[nt][1]);
    *(float2*)&g_v [oA] = make_float2(acc2[nt][0], acc2[nt][1]);
    *(float2*)&g_qk[oB] = make_float2(acc1[nt][2], acc1[nt][3]);
    *(float2*)&g_v [oB] = make_float2(acc2[nt][2], acc2[nt][3]);
  }
}

// ---------------- stage 3a: LSH bucket ids — warp-per-hash, 4 pos/thread ----------------
__global__ __launch_bounds__(256) void bucket_kernel(const float* __restrict__ rot){
  __shared__ float s_rot[1280];        // [f=32][h=8][i=5]
  __shared__ float s_q[128][33];
  int bh = blockIdx.x, pos0 = blockIdx.y*128;
  int tid = threadIdx.x;

  for (int i=tid;i<1280;i+=256) s_rot[i]=rot[i];
  {
    int row = tid>>1, fh = (tid&1)*16;
    const float* src = g_qk + ((size_t)bh*640 + pos0 + row)*32 + fh;
    #pragma unroll
    for (int u=0;u<16;u+=4){
      float4 v = *(const float4*)(src+u);
      s_q[row][fh+u]=v.x; s_q[row][fh+u+1]=v.y; s_q[row][fh+u+2]=v.z; s_q[row][fh+u+3]=v.w;
    }
  }
  __syncthreads();

  int h = tid>>5, l = tid&31;
  float r5[4][5];
  #pragma unroll
  for (int k=0;k<4;k++)
    #pragma unroll
    for (int i=0;i<5;i++) r5[k][i]=0.f;

  #pragma unroll 4
  for (int f=0;f<32;f++){
    const float* rp = s_rot + f*40 + h*5;   // warp-uniform -> broadcast
    float w0=rp[0], w1=rp[1], w2=rp[2], w3=rp[3], w4=rp[4];
    #pragma unroll
    for (int k=0;k<4;k++){
      float qf = s_q[l + 32*k][f];
      r5[k][0] += qf*w0; r5[k][1] += qf*w1; r5[k][2] += qf*w2;
      r5[k][3] += qf*w3; r5[k][4] += qf*w4;
    }
  }
  #pragma unroll
  for (int k=0;k<4;k++){
    float best = r5[k][0]; int bi = 0;
    #pragma unroll
    for (int i=1;i<5;i++) if (r5[k][i] > best){ best=r5[k][i]; bi=i; }
    #pragma unroll
    for (int i=0;i<5;i++){ float v = -r5[k][i]; if (v > best){ best=v; bi=5+i; } }
    g_bucket[(size_t)bh*NHASH*T + h*640 + pos0 + l + 32*k] = bi;
  }
}

// ---------------- stage 3b: stable counting sort per (bh, hash) — smem staged ----------------
__global__ __launch_bounds__(320) void sort_kernel(){
  __shared__ int s_bk[640];
  __shared__ int cnt[10], off[10];
  int bhh = blockIdx.x;
  const int* bk = g_bucket + bhh*640;
  for (int i=threadIdx.x;i<640;i+=320) s_bk[i]=bk[i];
  __syncthreads();

  int w = threadIdx.x>>5, lane = threadIdx.x&31;
  int count = 0;
  for (int base=0;base<640;base+=32){
    int bb = s_bk[base+lane];
    unsigned mask = __ballot_sync(0xffffffffu, bb==w);
    count += __popc(mask);
  }
  if (lane==0) cnt[w] = count;
  __syncthreads();
  if (threadIdx.x==0){
    int run=0;
    for (int b=0;b<10;b++){ off[b]=run; run+=cnt[b]; }
  }
  __syncthreads();
  int base_off = off[w]; int run = 0;
  int* out = g_sorted + bhh*640;
  for (int base=0;base<640;base+=32){
    int bb = s_bk[base+lane];
    unsigned mask = __ballot_sync(0xffffffffu, bb==w);
    if (bb==w){
      int slot = base_off + run + __popc(mask & ((1u<<lane)-1u));
      out[slot] = base+lane;
    }
    run += __popc(mask);
  }
}

// ---------------- stage 4: chunked attention, 3xTF32, k-permuted vectorized LDS ----------------
// smem floats: s_p [64][132]=8448 (aliased during dots by s_q [64][36] + s_k [128][36])
//              s_vT [32][132]=4224 | s_redm[128] | s_reds[128] | s_qt[64] | s_kt[128]
#define Q_PAD 36
#define K_PAD 36
#define P_PAD 132
#define VT_PAD 132
#define SMEM_ATTN ((64*P_PAD + 32*VT_PAD + 2*128)*4 + (64+128)*4)

__global__ __launch_bounds__(256) void attn_kernel(){
  extern __shared__ char smem_raw[];
  float* s_p    = (float*)smem_raw;          // [64][132]
  float* s_q    = s_p;                       // [64][36]  alias
  float* s_k    = s_p + 64*Q_PAD;            // [128][36] alias
  float* s_vT   = s_p + 64*P_PAD;            // [32][132] V transposed, k-permuted
  float* s_redm = s_vT + 32*VT_PAD;          // [2][64]
  float* s_reds = s_redm + 128;              // [2][64]
  int*   s_qt   = (int*)(s_reds + 128);      // [64]
  int*   s_kt   = s_qt + 64;                 // [128]

  int tid = threadIdx.x;
  int blk = blockIdx.x;
  int bh = blk / NCHUNK, c = blk % NCHUNK;
  int h  = c / 10;
  int pc = (c + NCHUNK - 1) % NCHUNK;
  int ph = pc / 10;
  const int* sortedbh = g_sorted + bh*NHASH*T;

  if (tid < 64)
    s_qt[tid] = sortedbh[h*640 + (c%10)*64 + tid];
  else if (tid < 192){
    int j = tid - 64;
    s_kt[j] = (j < 64) ? sortedbh[h*640 + (c%10)*64 + j]
                       : sortedbh[ph*640 + (pc%10)*64 + (j-64)];
  }
  __syncthreads();

  // Q [64][36], k-permuted columns
  {
    int i = tid >> 2, f0 = (tid & 3) * 8;
    const float* src = g_qk + ((size_t)bh*640 + s_qt[i])*32 + f0;
    float4 a = *(const float4*)src;
    float4 b = *(const float4*)(src+4);
    float vals[8] = {a.x,a.y,a.z,a.w,b.x,b.y,b.z,b.w};
    #pragma unroll
    for (int u=0;u<8;u++)
      s_q[i*Q_PAD + f0 + ((u&3)<<1) + ((u>>2)&1)] = vals[u];
  }
  // K [128][36], normalized, k-permuted columns
  {
    int j = tid >> 1, fh = (tid & 1) * 16;
    const float* src = g_qk + ((size_t)bh*640 + s_kt[j])*32 + fh;
    float buf[16]; float ss = 0.f;
    #pragma unroll
    for (int u=0;u<16;u+=4){
      float4 a = *(const float4*)(src+u);
      buf[u]=a.x; buf[u+1]=a.y; buf[u+2]=a.z; buf[u+3]=a.w;
      ss += a.x*a.x + a.y*a.y + a.z*a.z + a.w*a.w;
    }
    ss += __shfl_xor_sync(0xffffffffu, ss, 1);
    float inv = 1.f / fmaxf(sqrtf(ss), 1e-6f);
    #pragma unroll
    for (int u=0;u<16;u++)
      s_k[j*K_PAD + kperm(fh+u)] = buf[u]*inv;
  }
  // V transposed [32][132], k-permuted key index
  {
    int j = tid >> 1, fh = (tid & 1) * 16;
    int pj = kperm(j);
    const float* src = g_v + ((size_t)bh*640 + s_kt[j])*32 + fh;
    #pragma unroll
    for (int u=0;u<16;u+=4){
      float4 a = *(const float4*)(src+u);
      s_vT[(fh+u  )*VT_PAD + pj] = a.x;
      s_vT[(fh+u+1)*VT_PAD + pj] = a.y;
      s_vT[(fh+u+2)*VT_PAD + pj] = a.z;
      s_vT[(fh+u+3)*VT_PAD + pj] = a.w;
    }
  }
  __syncthreads();

  int warp = tid >> 5, lane = tid & 31;
  int wm = warp & 3, wn = warp >> 2;
  int g = lane >> 2, tig = lane & 3;
  int m0 = wm * 16;
  int rA = m0 + g, rB = m0 + g + 8;

  // ---- dots: S(16x64 per warp) = Q x K^T, 3xTF32, LDS.64 fragments ----
  float acc[8][4];
  #pragma unroll
  for (int nt=0;nt<8;nt++)
    #pragma unroll
    for (int u=0;u<4;u++) acc[nt][u] = 0.f;

  #pragma unroll
  for (int k0=0;k0<32;k0+=8){
    float2 qA = *(float2*)&s_q[rA*Q_PAD + k0 + 2*tig];
    float2 qB = *(float2*)&s_q[rB*Q_PAD + k0 + 2*tig];
    unsigned ah[4], al[4];
    tf32_split(qA.x, ah[0], al[0]);
    tf32_split(qB.x, ah[1], al[1]);
    tf32_split(qA.y, ah[2], al[2]);
    tf32_split(qB.y, ah[3], al[3]);
    #pragma unroll
    for (int nt=0;nt<8;nt++){
      int n0 = wn*64 + nt*8;
      float2 kv = *(float2*)&s_k[(n0+g)*K_PAD + k0 + 2*tig];
      unsigned bhh[2], bll[2];
      tf32_split(kv.x, bhh[0], bll[0]);
      tf32_split(kv.y, bhh[1], bll[1]);
      mma_tf32(acc[nt], ah, bhh);
      mma_tf32(acc[nt], al, bhh);
      mma_tf32(acc[nt], ah, bll);
    }
  }

  int qtA = s_qt[rA], qtB = s_qt[rB];
  #pragma unroll
  for (int nt=0;nt<8;nt++){
    int n0 = wn*64 + nt*8;
    int kt0 = s_kt[n0 + 2*tig], kt1 = s_kt[n0 + 2*tig + 1];
    acc[nt][0] = (kt0==qtA) ? -50000.f : acc[nt][0]*0.17677669529663687f;
    acc[nt][1] = (kt1==qtA) ? -50000.f : acc[nt][1]*0.17677669529663687f;
    acc[nt][2] = (kt0==qtB) ? -50000.f : acc[nt][2]*0.17677669529663687f;
    acc[nt][3] = (kt1==qtB) ? -50000.f : acc[nt][3]*0.17677669529663687f;
  }

  float mA=-INFINITY, mB=-INFINITY;
  #pragma unroll
  for (int nt=0;nt<8;nt++){
    mA = fmaxf(mA, fmaxf(acc[nt][0], acc[nt][1]));
    mB = fmaxf(mB, fmaxf(acc[nt][2], acc[nt][3]));
  }
  #pragma unroll
  for (int o=1;o<=2;o<<=1){
    mA = fmaxf(mA, __shfl_xor_sync(0xffffffffu, mA, o, 4));
    mB = fmaxf(mB, __shfl_xor_sync(0xffffffffu, mB, o, 4));
  }
  float sA=0.f, sB=0.f;
  #pragma unroll
  for (int nt=0;nt<8;nt++){
    acc[nt][0] = __expf(acc[nt][0]-mA);
    acc[nt][1] = __expf(acc[nt][1]-mA);
    acc[nt][2] = __expf(acc[nt][2]-mB);
    acc[nt][3] = __expf(acc[nt][3]-mB);
    sA += acc[nt][0] + acc[nt][1];
    sB += acc[nt][2] + acc[nt][3];
  }
  #pragma unroll
  for (int o=1;o<=2;o<<=1){
    sA += __shfl_xor_sync(0xffffffffu, sA, o, 4);
    sB += __shfl_xor_sync(0xffffffffu, sB, o, 4);
  }
  if (tig == 0){
    s_redm[wn*64 + rA] = mA;  s_reds[wn*64 + rA] = sA;
    s_redm[wn*64 + rB] = mB;  s_reds[wn*64 + rB] = sB;
  }
  __syncthreads();   // all dots-reads of s_q/s_k complete past this point

  float lseA, lseB;
  {
    float m0A = s_redm[rA], m1A = s_redm[64+rA];
    float mm = fmaxf(m0A, m1A);
    float ss = s_reds[rA]*__expf(m0A-mm) + s_reds[64+rA]*__expf(m1A-mm);
    lseA = mm + __logf(ss);
    float m0B = s_redm[rB], m1B = s_redm[64+rB];
    mm = fmaxf(m0B, m1B);
    ss = s_reds[rB]*__expf(m0B-mm) + s_reds[64+rB]*__expf(m1B-mm);
    lseB = mm + __logf(ss);
  }
  if (wn == 0 && tig == 0){
    g_logit[(bh*NHASH+h)*T + qtA] = lseA;
    g_logit[(bh*NHASH+h)*T + qtB] = lseB;
  }

  // probs into s_p with k-permuted columns (so PV A-fragments are LDS.64)
  float scA = __expf(mA - lseA);
  float scB = __expf(mB - lseB);
  int w0 = 2*tig, w1 = 2*tig + 1;
  int p0 = ((w0&3)<<1) + ((w0>>2)&1);
  int p1 = ((w1&3)<<1) + ((w1>>2)&1);
  #pragma unroll
  for (int nt=0;nt<8;nt++){
    int n0 = wn*64 + nt*8;
    s_p[rA*P_PAD + n0 + p0] = acc[nt][0]*scA;
    s_p[rA*P_PAD + n0 + p1] = acc[nt][1]*scA;
    s_p[rB*P_PAD + n0 + p0] = acc[nt][2]*scB;
    s_p[rB*P_PAD + n0 + p1] = acc[nt][3]*scB;
  }
  __syncthreads();

  // ---- PV: O(16x16 per warp) = P(16x128) x V(128x32), 3xTF32, LDS.64 fragments ----
  float o0[4] = {0.f,0.f,0.f,0.f};
  float o1[4] = {0.f,0.f,0.f,0.f};
  int d0 = wn*16;
  #pragma unroll 2
  for (int k0=0;k0<128;k0+=8){
    float2 pA = *(float2*)&s_p[rA*P_PAD + k0 + 2*tig];
    float2 pB = *(float2*)&s_p[rB*P_PAD + k0 + 2*tig];
    unsigned ah[4], al[4];
    tf32_split(pA.x, ah[0], al[0]);
    tf32_split(pB.x, ah[1], al[1]);
    tf32_split(pA.y, ah[2], al[2]);
    tf32_split(pB.y, ah[3], al[3]);
    float2 v0 = *(float2*)&s_vT[(d0+g  )*VT_PAD + k0 + 2*tig];
    float2 v1 = *(float2*)&s_vT[(d0+8+g)*VT_PAD + k0 + 2*tig];
    unsigned b0h[2], b0l[2], b1h[2], b1l[2];
    tf32_split(v0.x, b0h[0], b0l[0]);
    tf32_split(v0.y, b0h[1], b0l[1]);
    tf32_split(v1.x, b1h[0], b1l[0]);
    tf32_split(v1.y, b1h[1], b1l[1]);
    mma_tf32(o0, ah, b0h);
    mma_tf32(o0, al, b0h);
    mma_tf32(o0, ah, b0l);
    mma_tf32(o1, ah, b1h);
    mma_tf32(o1, al, b1h);
    mma_tf32(o1, ah, b1l);
  }
  {
    size_t base = (size_t)(bh*NHASH+h)*T;
    float* dA = g_ohash + (base + qtA)*32;
    float* dB = g_ohash + (base + qtB)*32;
    *(float2*)(dA + d0 + 2*tig)     = make_float2(o0[0], o0[1]);
    *(float2*)(dB + d0 + 2*tig)     = make_float2(o0[2], o0[3]);
    *(float2*)(dA + d0 + 8 + 2*tig) = make_float2(o1[0], o1[1]);
    *(float2*)(dB + d0 + 8 + 2*tig) = make_float2(o1[2], o1[3]);
  }
}

// ---------------- stage 5: combine hashes, merge heads (float4) ----------------
__global__ void combine_kernel(){
  int idx = blockIdx.x*blockDim.x + threadIdx.x;
  if (idx >= BHDIM*T*8) return;
  int dq  = idx & 7;
  int pos = (idx >> 3) % 640;
  int bh  = idx / (640*8);
  float l[NHASH];
  #pragma unroll
  for (int h=0;h<NHASH;h++) l[h] = g_logit[(bh*NHASH+h)*T + pos];
  float m = l[0];
  #pragma unroll
  for (int h=1;h<NHASH;h++) m = fmaxf(m, l[h]);
  float s = 0.f;
  float e[NHASH];
  #pragma unroll
  for (int h=0;h<NHASH;h++){ e[h] = __expf(l[h]-m); s += e[h]; }
  float inv = 1.f/s;
  float4 acc = make_float4(0.f,0.f,0.f,0.f);
  #pragma unroll
  for (int h=0;h<NHASH;h++){
    float w = e[h]*inv;
    float4 v = *(const float4*)(g_ohash + ((size_t)(bh*NHASH+h)*T + pos)*32 + dq*4);
    acc.x += w*v.x; acc.y += w*v.y; acc.z += w*v.z; acc.w += w*v.w;
  }
  int b = bh>>3, head = bh&7;
  *(float4*)(g_omerged + ((size_t)b*640 + pos)*256 + head*32 + dq*4) = acc;
}

// ---------------- stage 6: output GEMM + bias, 3xTF32, cp.async double-buffered ----------------
#define OUT_TILE (128*36 + 2*64*36)          // 9216 floats per stage
#define SMEM_OUT (2*OUT_TILE*4)              // 73.7 KB

__global__ __launch_bounds__(256) void gemm_out_tc(const float* __restrict__ bias,
                                                   float* __restrict__ out){
  extern __shared__ float sm[];
  int tid = threadIdx.x;
  int m0 = blockIdx.y*128, n0 = blockIdx.x*64;
  int warp = tid>>5, lane = tid&31;
  int g = lane>>2, tig = lane&3;
  int rA = warp*16 + g, rB = rA + 8;

  int lrow = tid>>1, lhalf = (tid&1)*16;
  int lbn  = tid>>2, lkq   = (tid&3)*8;

  float acc[8][4];
  #pragma unroll
  for (int nt=0;nt<8;nt++)
    #pragma unroll
    for (int u=0;u<4;u++) acc[nt][u]=0.f;

  auto load_tile = [&](int it, float* base){
    int kc = it*32;
    float* s_a  = base;
    float* s_bh = base + 128*36;
    float* s_bl = s_bh + 64*36;
    const float* asrc = g_omerged + (size_t)(m0+lrow)*EMBD + kc + lhalf;
    cp16(&s_a[lrow*36+lhalf],    asrc);
    cp16(&s_a[lrow*36+lhalf+4],  asrc+4);
    cp16(&s_a[lrow*36+lhalf+8],  asrc+8);
    cp16(&s_a[lrow*36+lhalf+12], asrc+12);
    size_t bo = (size_t)(n0+lbn)*EMBD + kc + lkq;
    cp16(&s_bh[lbn*36+lkq],   &g_woT_hi[bo]);
    cp16(&s_bh[lbn*36+lkq+4], &g_woT_hi[bo+4]);
    cp16(&s_bl[lbn*36+lkq],   &g_woT_lo[bo]);
    cp16(&s_bl[lbn*36+lkq+4], &g_woT_lo[bo+4]);
  };

  load_tile(0, sm);
  CP_COMMIT();

  for (int it=0; it<8; it++){
    if (it < 7){
      load_tile(it+1, sm + ((it+1)&1)*OUT_TILE);
      CP_COMMIT();
      CP_WAIT1();
    } else {
      CP_WAIT0();
    }
    __syncthreads();

    float* base = sm + (it&1)*OUT_TILE;
    float* s_a  = base;
    float* s_bh = base + 128*36;
    float* s_bl = s_bh + 64*36;

    #pragma unroll
    for (int kk=0;kk<32;kk+=8){
      unsigned ah[4], al[4];
      tf32_split(s_a[rA*36+kk+tig],   ah[0], al[0]);
      tf32_split(s_a[rB*36+kk+tig],   ah[1], al[1]);
      tf32_split(s_a[rA*36+kk+tig+4], ah[2], al[2]);
      tf32_split(s_a[rB*36+kk+tig+4], ah[3], al[3]);
      #pragma unroll
      for (int nt=0;nt<8;nt++){
        int nr = nt*8 + g;
        unsigned bhv[2] = { fu(s_bh[nr*36+kk+tig]), fu(s_bh[nr*36+kk+tig+4]) };
        unsigned blv[2] = { fu(s_bl[nr*36+kk+tig]), fu(s_bl[nr*36+kk+tig+4]) };
        mma_tf32(acc[nt], ah, bhv);
        mma_tf32(acc[nt], al, bhv);
        mma_tf32(acc[nt], ah, blv);
      }
    }
    __syncthreads();
  }

  int rowA = m0 + rA, rowB = m0 + rB;
  #pragma unroll
  for (int nt=0;nt<8;nt++){
    int col = n0 + nt*8 + 2*tig;
    float b0 = __ldg(bias+col), b1 = __ldg(bias+col+1);
    *(float2*)&out[(size_t)rowA*EMBD + col] = make_float2(acc[nt][0]+b0, acc[nt][1]+b1);
    *(float2*)&out[(size_t)rowB*EMBD + col] = make_float2(acc[nt][2]+b0, acc[nt][3]+b1);
  }
}

// ---------------- launch ----------------
extern "C" void kernel_launch(void* const* d_in, const int* in_sizes, int n_in,
                              void* d_out, int out_size){
  const float* x     = (const float*)d_in[0];
  const float* w_qk  = (const float*)d_in[1];
  const float* w_v   = (const float*)d_in[2];
  const float* w_out = (const float*)d_in[3];
  const float* b_out = (const float*)d_in[4];
  const float* rot   = (const float*)d_in[5];
  float* out = (float*)d_out;

  wsplit_kernel<<<dim3(8,8,3), dim3(32,8)>>>(w_qk, w_v, w_out);
  frontend_kernel<<<BATCH*128, 256>>>(x);
  cudaFuncSetAttribute(gemm_qkv_tc, cudaFuncAttributeMaxDynamicSharedMemorySize, SMEM_QKV);
  gemm_qkv_tc<<<dim3(4,80), 256, SMEM_QKV>>>();
  bucket_kernel<<<dim3(BHDIM, T/128), 256>>>(rot);
  sort_kernel<<<BHDIM*NHASH, 320>>>();
  cudaFuncSetAttribute(attn_kernel, cudaFuncAttributeMaxDynamicSharedMemorySize, SMEM_ATTN);
  attn_kernel<<<BHDIM*NCHUNK, 256, SMEM_ATTN>>>();
  combine_kernel<<<(BHDIM*T*8+255)/256, 256>>>();
  cudaFuncSetAttribute(gemm_out_tc, cudaFuncAttributeMaxDynamicSharedMemorySize, SMEM_OUT);
  gemm_out_tc<<<dim3(4,80), 256, SMEM_OUT>>>(b_out, out);
}

// round 13
// speedup vs baseline: 1.1246x; 1.1246x over previous
#include <cuda_runtime.h>
#include <math.h>

#define BATCH   16
#define T       640
#define EMBD    256
#define HEADS   8
#define DHDIM   32
#define BHDIM   128      // BATCH*HEADS
#define NHASH   8
#define NCHUNK  80
#define NROWS   10240    // BATCH*T

// ---------------- scratch (device globals; no allocation allowed) ----------------
__device__ float g_tokens[NROWS*EMBD];
__device__ float g_qk[BHDIM*T*DHDIM];
__device__ float g_v [BHDIM*T*DHDIM];
__device__ int   g_bucket[BHDIM*NHASH*T];
__device__ int   g_sorted[BHDIM*NHASH*T];
__device__ float g_ohash[(size_t)BHDIM*NHASH*T*DHDIM];
__device__ float g_logit[BHDIM*NHASH*T];
__device__ float g_omerged[NROWS*EMBD];
// pre-transposed + pre-split weights: [n][k] layout, hi/lo planes
__device__ float g_wqkT_hi[EMBD*EMBD], g_wqkT_lo[EMBD*EMBD];
__device__ float g_wvT_hi [EMBD*EMBD], g_wvT_lo [EMBD*EMBD];
__device__ float g_woT_hi [EMBD*EMBD], g_woT_lo [EMBD*EMBD];

// ---------------- tf32 mma.sync helpers ----------------
__device__ __forceinline__ void mma_tf32(float* d, const unsigned* a, const unsigned* b){
  asm volatile(
    "mma.sync.aligned.m16n8k8.row.col.f32.tf32.tf32.f32 "
    "{%0,%1,%2,%3}, {%4,%5,%6,%7}, {%8,%9}, {%0,%1,%2,%3};"
    : "+f"(d[0]), "+f"(d[1]), "+f"(d[2]), "+f"(d[3])
    : "r"(a[0]), "r"(a[1]), "r"(a[2]), "r"(a[3]), "r"(b[0]), "r"(b[1]));
}
// cheap split: hi = x with low 13 mantissa bits zeroed (exact tf32 value), lo = x - hi
__device__ __forceinline__ void tf32_split(float x, unsigned &hi, unsigned &lo){
  unsigned hb = __float_as_uint(x) & 0xFFFFE000u;
  hi = hb;
  lo = __float_as_uint(x - __uint_as_float(hb));
}
// round-to-nearest tf32 (zero-mean rounding, used where the lo-term is dropped)
__device__ __forceinline__ unsigned tf32_rna(float x){
  unsigned u; asm("cvt.rna.tf32.f32 %0, %1;" : "=r"(u) : "f"(x)); return u;
}
__device__ __forceinline__ unsigned fu(float x){ return __float_as_uint(x); }

// ---------------- stage 0: weight transpose + split ----------------
__global__ void wsplit_kernel(const float* __restrict__ wqk,
                              const float* __restrict__ wv,
                              const float* __restrict__ wo){
  __shared__ float tile[32][33];
  int z = blockIdx.z;
  const float* src = (z==0) ? wqk : (z==1) ? wv : wo;
  float* dh = (z==0) ? g_wqkT_hi : (z==1) ? g_wvT_hi : g_woT_hi;
  float* dl = (z==0) ? g_wqkT_lo : (z==1) ? g_wvT_lo : g_woT_lo;
  int n0 = blockIdx.x*32, k0 = blockIdx.y*32;
  #pragma unroll
  for (int r=0;r<4;r++){
    int k = threadIdx.y + r*8;
    tile[k][threadIdx.x] = src[(k0+k)*EMBD + n0 + threadIdx.x];
  }
  __syncthreads();
  #pragma unroll
  for (int r=0;r<4;r++){
    int n = threadIdx.y + r*8;
    float v = tile[threadIdx.x][n];
    float hv = __uint_as_float(__float_as_uint(v) & 0xFFFFE000u);
    int oi = (n0+n)*EMBD + k0 + threadIdx.x;
    dh[oi] = hv;
    dl[oi] = v - hv;
  }
}

// ---------------- stage 1: maxpool + Haar DWT -> tokens (smem tiled) ----------------
__global__ __launch_bounds__(256) void frontend_kernel(const float* __restrict__ x){
  __shared__ float s_x[32][33];
  int plane = blockIdx.x;            // b*128 + ch
  int b = plane >> 7, ch = plane & 127;
  const float* xp = x + (size_t)plane*1024;
  int t = threadIdx.x;

  {
    float4 v = *(const float4*)(xp + t*4);
    int r = t >> 3, c4 = (t & 7)*4;
    s_x[r][c4]=v.x; s_x[r][c4+1]=v.y; s_x[r][c4+2]=v.z; s_x[r][c4+3]=v.w;
  }
  __syncthreads();

  int i = t >> 4, j = t & 15;
  float m = -INFINITY;
  int r0 = 2*i-1, c0 = 2*j-1;
  #pragma unroll
  for (int dr=0;dr<3;dr++){
    int r = r0+dr; if (r<0 || r>31) continue;
    #pragma unroll
    for (int dc=0;dc<3;dc++){
      int cc = c0+dc; if (cc<0 || cc>31) continue;
      m = fmaxf(m, s_x[r][cc]);
    }
  }
  float a  = s_x[2*i][2*j];
  float bb = s_x[2*i][2*j+1];
  float c  = s_x[2*i+1][2*j];
  float d  = s_x[2*i+1][2*j+1];
  float ll = (a+bb+c+d)*0.5f;
  float lh = (a-bb+c-d)*0.5f;
  float hl = (a+bb-c-d)*0.5f;
  float hh = (a-bb-c+d)*0.5f;

  size_t rowbase = (size_t)b*640;
  g_tokens[(rowbase + ch      )*256 + t] = m;
  g_tokens[(rowbase + 128 + ch)*256 + t] = ll;
  g_tokens[(rowbase + 256 + ch)*256 + t] = lh;
  g_tokens[(rowbase + 384 + ch)*256 + t] = hl;
  g_tokens[(rowbase + 512 + ch)*256 + t] = hh;
}

// ---------------- stage 2: fused qk/v GEMM, 3xTF32 tensor cores ----------------
#define SMEM_QKV ((128*36 + 4*64*36)*4)

__global__ __launch_bounds__(256) void gemm_qkv_tc(){
  extern __shared__ float sm[];
  float* s_a   = sm;                 // [128][36]
  float* s_b1h = s_a   + 128*36;     // [64][36]
  float* s_b1l = s_b1h + 64*36;
  float* s_b2h = s_b1l + 64*36;
  float* s_b2l = s_b2h + 64*36;

  int tid = threadIdx.x;
  int m0 = blockIdx.y*128, n0 = blockIdx.x*64;
  int warp = tid>>5, lane = tid&31;
  int g = lane>>2, tig = lane&3;
  int rA = warp*16 + g, rB = rA + 8;

  float acc1[8][4], acc2[8][4];
  #pragma unroll
  for (int nt=0;nt<8;nt++)
    #pragma unroll
    for (int u=0;u<4;u++){ acc1[nt][u]=0.f; acc2[nt][u]=0.f; }

  for (int kc=0;kc<EMBD;kc+=32){
    __syncthreads();
    {
      int row = tid>>1, half = (tid&1)*16;
      const float* asrc = g_tokens + (size_t)(m0+row)*EMBD + kc + half;
      #pragma unroll
      for (int u=0;u<16;u+=4)
        *(float4*)&s_a[row*36 + half + u] = *(const float4*)(asrc+u);
    }
    {
      int n = tid>>2, kq = (tid&3)*8;
      size_t bo = (size_t)(n0+n)*EMBD + kc + kq;
      *(float4*)&s_b1h[n*36+kq]   = *(const float4*)&g_wqkT_hi[bo];
      *(float4*)&s_b1h[n*36+kq+4] = *(const float4*)&g_wqkT_hi[bo+4];
      *(float4*)&s_b1l[n*36+kq]   = *(const float4*)&g_wqkT_lo[bo];
      *(float4*)&s_b1l[n*36+kq+4] = *(const float4*)&g_wqkT_lo[bo+4];
      *(float4*)&s_b2h[n*36+kq]   = *(const float4*)&g_wvT_hi[bo];
      *(float4*)&s_b2h[n*36+kq+4] = *(const float4*)&g_wvT_hi[bo+4];
      *(float4*)&s_b2l[n*36+kq]   = *(const float4*)&g_wvT_lo[bo];
      *(float4*)&s_b2l[n*36+kq+4] = *(const float4*)&g_wvT_lo[bo+4];
    }
    __syncthreads();

    #pragma unroll
    for (int kk=0;kk<32;kk+=8){
      unsigned ah[4], al[4];
      tf32_split(s_a[rA*36+kk+tig],   ah[0], al[0]);
      tf32_split(s_a[rB*36+kk+tig],   ah[1], al[1]);
      tf32_split(s_a[rA*36+kk+tig+4], ah[2], al[2]);
      tf32_split(s_a[rB*36+kk+tig+4], ah[3], al[3]);
      #pragma unroll
      for (int nt=0;nt<8;nt++){
        int nr = nt*8 + g;
        unsigned b1h[2] = { fu(s_b1h[nr*36+kk+tig]), fu(s_b1h[nr*36+kk+tig+4]) };
        unsigned b1l[2] = { fu(s_b1l[nr*36+kk+tig]), fu(s_b1l[nr*36+kk+tig+4]) };
        mma_tf32(acc1[nt], ah, b1h);
        mma_tf32(acc1[nt], al, b1h);
        mma_tf32(acc1[nt], ah, b1l);
        unsigned b2h[2] = { fu(s_b2h[nr*36+kk+tig]), fu(s_b2h[nr*36+kk+tig+4]) };
        unsigned b2l[2] = { fu(s_b2l[nr*36+kk+tig]), fu(s_b2l[nr*36+kk+tig+4]) };
        mma_tf32(acc2[nt], ah, b2h);
        mma_tf32(acc2[nt], al, b2h);
        mma_tf32(acc2[nt], ah, b2l);
      }
    }
  }
  int rowA = m0 + rA, rowB = m0 + rB;
  int bA = rowA/640, tokA = rowA - bA*640;
  int bB = rowB/640, tokB = rowB - bB*640;
  #pragma unroll
  for (int nt=0;nt<8;nt++){
    int col = n0 + nt*8 + 2*tig;
    int head = col>>5, dh = col&31;
    size_t oA = ((size_t)(bA*8+head)*640 + tokA)*32 + dh;
    size_t oB = ((size_t)(bB*8+head)*640 + tokB)*32 + dh;
    *(float2*)&g_qk[oA] = make_float2(acc1[nt][0], acc1[nt][1]);
    *(float2*)&g_v [oA] = make_float2(acc2[nt][0], acc2[nt][1]);
    *(float2*)&g_qk[oB] = make_float2(acc1[nt][2], acc1[nt][3]);
    *(float2*)&g_v [oB] = make_float2(acc2[nt][2], acc2[nt][3]);
  }
}

// ---------------- stage 3a: LSH bucket ids — warp-per-hash, 4 pos/thread ----------------
__global__ __launch_bounds__(256) void bucket_kernel(const float* __restrict__ rot){
  __shared__ float s_rot[1280];        // [f=32][h=8][i=5]
  __shared__ float s_q[128][33];
  int bh = blockIdx.x, pos0 = blockIdx.y*128;
  int tid = threadIdx.x;

  for (int i=tid;i<1280;i+=256) s_rot[i]=rot[i];
  {
    int row = tid>>1, fh = (tid&1)*16;
    const float* src = g_qk + ((size_t)bh*640 + pos0 + row)*32 + fh;
    #pragma unroll
    for (int u=0;u<16;u+=4){
      float4 v = *(const float4*)(src+u);
      s_q[row][fh+u]=v.x; s_q[row][fh+u+1]=v.y; s_q[row][fh+u+2]=v.z; s_q[row][fh+u+3]=v.w;
    }
  }
  __syncthreads();

  int h = tid>>5, l = tid&31;
  float r5[4][5];
  #pragma unroll
  for (int k=0;k<4;k++)
    #pragma unroll
    for (int i=0;i<5;i++) r5[k][i]=0.f;

  #pragma unroll 4
  for (int f=0;f<32;f++){
    const float* rp = s_rot + f*40 + h*5;   // warp-uniform -> broadcast
    float w0=rp[0], w1=rp[1], w2=rp[2], w3=rp[3], w4=rp[4];
    #pragma unroll
    for (int k=0;k<4;k++){
      float qf = s_q[l + 32*k][f];
      r5[k][0] += qf*w0; r5[k][1] += qf*w1; r5[k][2] += qf*w2;
      r5[k][3] += qf*w3; r5[k][4] += qf*w4;
    }
  }
  #pragma unroll
  for (int k=0;k<4;k++){
    float best = r5[k][0]; int bi = 0;
    #pragma unroll
    for (int i=1;i<5;i++) if (r5[k][i] > best){ best=r5[k][i]; bi=i; }
    #pragma unroll
    for (int i=0;i<5;i++){ float v = -r5[k][i]; if (v > best){ best=v; bi=5+i; } }
    g_bucket[(size_t)bh*NHASH*T + h*640 + pos0 + l + 32*k] = bi;
  }
}

// ---------------- stage 3b: stable counting sort per (bh, hash) — smem staged ----------------
__global__ __launch_bounds__(320) void sort_kernel(){
  __shared__ int s_bk[640];
  __shared__ int cnt[10], off[10];
  int bhh = blockIdx.x;
  const int* bk = g_bucket + bhh*640;
  for (int i=threadIdx.x;i<640;i+=320) s_bk[i]=bk[i];
  __syncthreads();

  int w = threadIdx.x>>5, lane = threadIdx.x&31;
  int count = 0;
  for (int base=0;base<640;base+=32){
    int bb = s_bk[base+lane];
    unsigned mask = __ballot_sync(0xffffffffu, bb==w);
    count += __popc(mask);
  }
  if (lane==0) cnt[w] = count;
  __syncthreads();
  if (threadIdx.x==0){
    int run=0;
    for (int b=0;b<10;b++){ off[b]=run; run+=cnt[b]; }
  }
  __syncthreads();
  int base_off = off[w]; int run = 0;
  int* out = g_sorted + bhh*640;
  for (int base=0;base<640;base+=32){
    int bb = s_bk[base+lane];
    unsigned mask = __ballot_sync(0xffffffffu, bb==w);
    if (bb==w){
      int slot = base_off + run + __popc(mask & ((1u<<lane)-1u));
      out[slot] = base+lane;
    }
    run += __popc(mask);
  }
}

// ---------------- stage 4: chunked attention, 3xTF32 dots + 2xTF32-V PV ----------------
#define Q_PAD 36
#define K_PAD 36
#define V_PAD 40
#define P_PAD 132
#define SMEM_ATTN ((64*P_PAD + 128*V_PAD + 2*128)*4 + (64+128)*4)

__global__ __launch_bounds__(256) void attn_kernel(){
  extern __shared__ char smem_raw[];
  float* s_p    = (float*)smem_raw;          // [64][132]
  float* s_q    = s_p;                       // [64][36]  alias
  float* s_k    = s_p + 64*Q_PAD;            // [128][36] alias
  float* s_v    = s_p + 64*P_PAD;            // [128][40]
  float* s_redm = s_v + 128*V_PAD;           // [2][64]
  float* s_reds = s_redm + 128;              // [2][64]
  int*   s_qt   = (int*)(s_reds + 128);      // [64]
  int*   s_kt   = s_qt + 64;                 // [128]

  int tid = threadIdx.x;
  int blk = blockIdx.x;
  int bh = blk / NCHUNK, c = blk % NCHUNK;
  int h  = c / 10;
  int pc = (c + NCHUNK - 1) % NCHUNK;
  int ph = pc / 10;
  const int* sortedbh = g_sorted + bh*NHASH*T;

  if (tid < 64)
    s_qt[tid] = sortedbh[h*640 + (c%10)*64 + tid];
  else if (tid < 192){
    int j = tid - 64;
    s_kt[j] = (j < 64) ? sortedbh[h*640 + (c%10)*64 + j]
                       : sortedbh[ph*640 + (pc%10)*64 + (j-64)];
  }
  __syncthreads();

  {
    int i = tid >> 2, f0 = (tid & 3) * 8;
    const float* src = g_qk + ((size_t)bh*640 + s_qt[i])*32 + f0;
    *(float4*)&s_q[i*Q_PAD + f0]     = *(const float4*)src;
    *(float4*)&s_q[i*Q_PAD + f0 + 4] = *(const float4*)(src+4);
  }
  {
    int j = tid >> 1, fh = (tid & 1) * 16;
    const float* src = g_qk + ((size_t)bh*640 + s_kt[j])*32 + fh;
    float buf[16]; float ss = 0.f;
    #pragma unroll
    for (int u=0;u<16;u+=4){
      float4 a = *(const float4*)(src+u);
      buf[u]=a.x; buf[u+1]=a.y; buf[u+2]=a.z; buf[u+3]=a.w;
      ss += a.x*a.x + a.y*a.y + a.z*a.z + a.w*a.w;
    }
    ss += __shfl_xor_sync(0xffffffffu, ss, 1);
    float inv = 1.f / fmaxf(sqrtf(ss), 1e-6f);
    #pragma unroll
    for (int u=0;u<16;u+=4)
      *(float4*)&s_k[j*K_PAD + fh + u] =
        make_float4(buf[u]*inv, buf[u+1]*inv, buf[u+2]*inv, buf[u+3]*inv);
  }
  {
    int j = tid >> 1, fh = (tid & 1) * 16;
    const float* src = g_v + ((size_t)bh*640 + s_kt[j])*32 + fh;
    #pragma unroll
    for (int u=0;u<16;u+=4)
      *(float4*)&s_v[j*V_PAD + fh + u] = *(const float4*)(src+u);
  }
  __syncthreads();

  int warp = tid >> 5, lane = tid & 31;
  int wm = warp & 3, wn = warp >> 2;
  int g = lane >> 2, tig = lane & 3;
  int m0 = wm * 16;
  int rA = m0 + g, rB = m0 + g + 8;

  // ---- dots: S(16x64 per warp) = Q x K^T, full 3xTF32 ----
  float acc[8][4];
  #pragma unroll
  for (int nt=0;nt<8;nt++)
    #pragma unroll
    for (int u=0;u<4;u++) acc[nt][u] = 0.f;

  #pragma unroll
  for (int k0=0;k0<32;k0+=8){
    unsigned ah[4], al[4];
    tf32_split(s_q[rA*Q_PAD + k0 + tig],     ah[0], al[0]);
    tf32_split(s_q[rB*Q_PAD + k0 + tig],     ah[1], al[1]);
    tf32_split(s_q[rA*Q_PAD + k0 + tig + 4], ah[2], al[2]);
    tf32_split(s_q[rB*Q_PAD + k0 + tig + 4], ah[3], al[3]);
    #pragma unroll
    for (int nt=0;nt<8;nt++){
      int n0 = wn*64 + nt*8;
      unsigned bhh[2], bll[2];
      tf32_split(s_k[(n0+g)*K_PAD + k0 + tig],     bhh[0], bll[0]);
      tf32_split(s_k[(n0+g)*K_PAD + k0 + tig + 4], bhh[1], bll[1]);
      mma_tf32(acc[nt], ah, bhh);
      mma_tf32(acc[nt], al, bhh);
      mma_tf32(acc[nt], ah, bll);
    }
  }

  int qtA = s_qt[rA], qtB = s_qt[rB];
  #pragma unroll
  for (int nt=0;nt<8;nt++){
    int n0 = wn*64 + nt*8;
    int kt0 = s_kt[n0 + 2*tig], kt1 = s_kt[n0 + 2*tig + 1];
    acc[nt][0] = (kt0==qtA) ? -50000.f : acc[nt][0]*0.17677669529663687f;
    acc[nt][1] = (kt1==qtA) ? -50000.f : acc[nt][1]*0.17677669529663687f;
    acc[nt][2] = (kt0==qtB) ? -50000.f : acc[nt][2]*0.17677669529663687f;
    acc[nt][3] = (kt1==qtB) ? -50000.f : acc[nt][3]*0.17677669529663687f;
  }

  float mA=-INFINITY, mB=-INFINITY;
  #pragma unroll
  for (int nt=0;nt<8;nt++){
    mA = fmaxf(mA, fmaxf(acc[nt][0], acc[nt][1]));
    mB = fmaxf(mB, fmaxf(acc[nt][2], acc[nt][3]));
  }
  #pragma unroll
  for (int o=1;o<=2;o<<=1){
    mA = fmaxf(mA, __shfl_xor_sync(0xffffffffu, mA, o, 4));
    mB = fmaxf(mB, __shfl_xor_sync(0xffffffffu, mB, o, 4));
  }
  float sA=0.f, sB=0.f;
  #pragma unroll
  for (int nt=0;nt<8;nt++){
    acc[nt][0] = __expf(acc[nt][0]-mA);
    acc[nt][1] = __expf(acc[nt][1]-mA);
    acc[nt][2] = __expf(acc[nt][2]-mB);
    acc[nt][3] = __expf(acc[nt][3]-mB);
    sA += acc[nt][0] + acc[nt][1];
    sB += acc[nt][2] + acc[nt][3];
  }
  #pragma unroll
  for (int o=1;o<=2;o<<=1){
    sA += __shfl_xor_sync(0xffffffffu, sA, o, 4);
    sB += __shfl_xor_sync(0xffffffffu, sB, o, 4);
  }
  if (tig == 0){
    s_redm[wn*64 + rA] = mA;  s_reds[wn*64 + rA] = sA;
    s_redm[wn*64 + rB] = mB;  s_reds[wn*64 + rB] = sB;
  }
  __syncthreads();

  float lseA, lseB;
  {
    float m0A = s_redm[rA], m1A = s_redm[64+rA];
    float mm = fmaxf(m0A, m1A);
    float ss = s_reds[rA]*__expf(m0A-mm) + s_reds[64+rA]*__expf(m1A-mm);
    lseA = mm + __logf(ss);
    float m0B = s_redm[rB], m1B = s_redm[64+rB];
    mm = fmaxf(m0B, m1B);
    ss = s_reds[rB]*__expf(m0B-mm) + s_reds[64+rB]*__expf(m1B-mm);
    lseB = mm + __logf(ss);
  }
  if (wn == 0 && tig == 0){
    g_logit[(bh*NHASH+h)*T + qtA] = lseA;
    g_logit[(bh*NHASH+h)*T + qtB] = lseB;
  }

  float scA = __expf(mA - lseA);
  float scB = __expf(mB - lseB);
  #pragma unroll
  for (int nt=0;nt<8;nt++){
    int n0 = wn*64 + nt*8;
    *(float2*)&s_p[rA*P_PAD + n0 + 2*tig] =
      make_float2(acc[nt][0]*scA, acc[nt][1]*scA);
    *(float2*)&s_p[rB*P_PAD + n0 + 2*tig] =
      make_float2(acc[nt][2]*scB, acc[nt][3]*scB);
  }
  __syncthreads();

  // ---- PV: probs exact-split, V as single rna-tf32 (lo-term dropped) ----
  float o0[4] = {0.f,0.f,0.f,0.f};
  float o1[4] = {0.f,0.f,0.f,0.f};
  int d0 = wn*16;
  #pragma unroll 2
  for (int k0=0;k0<128;k0+=8){
    unsigned ah[4], al[4];
    tf32_split(s_p[rA*P_PAD + k0 + tig],     ah[0], al[0]);
    tf32_split(s_p[rB*P_PAD + k0 + tig],     ah[1], al[1]);
    tf32_split(s_p[rA*P_PAD + k0 + tig + 4], ah[2], al[2]);
    tf32_split(s_p[rB*P_PAD + k0 + tig + 4], ah[3], al[3]);
    unsigned b0h[2], b1h[2];
    b0h[0] = tf32_rna(s_v[(k0+tig)*V_PAD   + d0 + g]);
    b0h[1] = tf32_rna(s_v[(k0+tig+4)*V_PAD + d0 + g]);
    b1h[0] = tf32_rna(s_v[(k0+tig)*V_PAD   + d0 + 8 + g]);
    b1h[1] = tf32_rna(s_v[(k0+tig+4)*V_PAD + d0 + 8 + g]);
    mma_tf32(o0, ah, b0h);
    mma_tf32(o0, al, b0h);
    mma_tf32(o1, ah, b1h);
    mma_tf32(o1, al, b1h);
  }
  {
    size_t base = (size_t)(bh*NHASH+h)*T;
    float* dA = g_ohash + (base + qtA)*32;
    float* dB = g_ohash + (base + qtB)*32;
    *(float2*)(dA + d0 + 2*tig)     = make_float2(o0[0], o0[1]);
    *(float2*)(dB + d0 + 2*tig)     = make_float2(o0[2], o0[3]);
    *(float2*)(dA + d0 + 8 + 2*tig) = make_float2(o1[0], o1[1]);
    *(float2*)(dB + d0 + 8 + 2*tig) = make_float2(o1[2], o1[3]);
  }
}

// ---------------- stage 5: combine hashes, merge heads (float4) ----------------
__global__ void combine_kernel(){
  int idx = blockIdx.x*blockDim.x + threadIdx.x;
  if (idx >= BHDIM*T*8) return;
  int dq  = idx & 7;
  int pos = (idx >> 3) % 640;
  int bh  = idx / (640*8);
  float l[NHASH];
  #pragma unroll
  for (int h=0;h<NHASH;h++) l[h] = g_logit[(bh*NHASH+h)*T + pos];
  float m = l[0];
  #pragma unroll
  for (int h=1;h<NHASH;h++) m = fmaxf(m, l[h]);
  float s = 0.f;
  float e[NHASH];
  #pragma unroll
  for (int h=0;h<NHASH;h++){ e[h] = __expf(l[h]-m); s += e[h]; }
  float inv = 1.f/s;
  float4 acc = make_float4(0.f,0.f,0.f,0.f);
  #pragma unroll
  for (int h=0;h<NHASH;h++){
    float w = e[h]*inv;
    float4 v = *(const float4*)(g_ohash + ((size_t)(bh*NHASH+h)*T + pos)*32 + dq*4);
    acc.x += w*v.x; acc.y += w*v.y; acc.z += w*v.z; acc.w += w*v.w;
  }
  int b = bh>>3, head = bh&7;
  *(float4*)(g_omerged + ((size_t)b*640 + pos)*256 + head*32 + dq*4) = acc;
}

// ---------------- stage 6: output GEMM + bias, 3xTF32 tensor cores ----------------
__global__ __launch_bounds__(256) void gemm_out_tc(const float* __restrict__ bias,
                                                   float* __restrict__ out){
  __shared__ float s_a[128*36];
  __shared__ float s_bh[64*36];
  __shared__ float s_bl[64*36];

  int tid = threadIdx.x;
  int m0 = blockIdx.y*128, n0 = blockIdx.x*64;
  int warp = tid>>5, lane = tid&31;
  int g = lane>>2, tig = lane&3;
  int rA = warp*16 + g, rB = rA + 8;

  float acc[8][4];
  #pragma unroll
  for (int nt=0;nt<8;nt++)
    #pragma unroll
    for (int u=0;u<4;u++) acc[nt][u]=0.f;

  for (int kc=0;kc<EMBD;kc+=32){
    __syncthreads();
    {
      int row = tid>>1, half = (tid&1)*16;
      const float* asrc = g_omerged + (size_t)(m0+row)*EMBD + kc + half;
      #pragma unroll
      for (int u=0;u<16;u+=4)
        *(float4*)&s_a[row*36 + half + u] = *(const float4*)(asrc+u);
    }
    {
      int n = tid>>2, kq = (tid&3)*8;
      size_t bo = (size_t)(n0+n)*EMBD + kc + kq;
      *(float4*)&s_bh[n*36+kq]   = *(const float4*)&g_woT_hi[bo];
      *(float4*)&s_bh[n*36+kq+4] = *(const float4*)&g_woT_hi[bo+4];
      *(float4*)&s_bl[n*36+kq]   = *(const float4*)&g_woT_lo[bo];
      *(float4*)&s_bl[n*36+kq+4] = *(const float4*)&g_woT_lo[bo+4];
    }
    __syncthreads();

    #pragma unroll
    for (int kk=0;kk<32;kk+=8){
      unsigned ah[4], al[4];
      tf32_split(s_a[rA*36+kk+tig],   ah[0], al[0]);
      tf32_split(s_a[rB*36+kk+tig],   ah[1], al[1]);
      tf32_split(s_a[rA*36+kk+tig+4], ah[2], al[2]);
      tf32_split(s_a[rB*36+kk+tig+4], ah[3], al[3]);
      #pragma unroll
      for (int nt=0;nt<8;nt++){
        int nr = nt*8 + g;
        unsigned bhv[2] = { fu(s_bh[nr*36+kk+tig]), fu(s_bh[nr*36+kk+tig+4]) };
        unsigned blv[2] = { fu(s_bl[nr*36+kk+tig]), fu(s_bl[nr*36+kk+tig+4]) };
        mma_tf32(acc[nt], ah, bhv);
        mma_tf32(acc[nt], al, bhv);
        mma_tf32(acc[nt], ah, blv);
      }
    }
  }
  int rowA = m0 + rA, rowB = m0 + rB;
  #pragma unroll
  for (int nt=0;nt<8;nt++){
    int col = n0 + nt*8 + 2*tig;
    float b0 = __ldg(bias+col), b1 = __ldg(bias+col+1);
    *(float2*)&out[(size_t)rowA*EMBD + col] = make_float2(acc[nt][0]+b0, acc[nt][1]+b1);
    *(float2*)&out[(size_t)rowB*EMBD + col] = make_float2(acc[nt][2]+b0, acc[nt][3]+b1);
  }
}

// ---------------- launch ----------------
extern "C" void kernel_launch(void* const* d_in, const int* in_sizes, int n_in,
                              void* d_out, int out_size){
  const float* x     = (const float*)d_in[0];
  const float* w_qk  = (const float*)d_in[1];
  const float* w_v   = (const float*)d_in[2];
  const float* w_out = (const float*)d_in[3];
  const float* b_out = (const float*)d_in[4];
  const float* rot   = (const float*)d_in[5];
  float* out = (float*)d_out;

  wsplit_kernel<<<dim3(8,8,3), dim3(32,8)>>>(w_qk, w_v, w_out);
  frontend_kernel<<<BATCH*128, 256>>>(x);
  cudaFuncSetAttribute(gemm_qkv_tc, cudaFuncAttributeMaxDynamicSharedMemorySize, SMEM_QKV);
  gemm_qkv_tc<<<dim3(4,80), 256, SMEM_QKV>>>();
  bucket_kernel<<<dim3(BHDIM, T/128), 256>>>(rot);
  sort_kernel<<<BHDIM*NHASH, 320>>>();
  cudaFuncSetAttribute(attn_kernel, cudaFuncAttributeMaxDynamicSharedMemorySize, SMEM_ATTN);
  attn_kernel<<<BHDIM*NCHUNK, 256, SMEM_ATTN>>>();
  combine_kernel<<<(BHDIM*T*8+255)/256, 256>>>();
  gemm_out_tc<<<dim3(4,80), 256>>>(b_out, out);
}

// round 14
// speedup vs baseline: 1.1572x; 1.0290x over previous
#include <cuda_runtime.h>
#include <math.h>

#define BATCH   16
#define T       640
#define EMBD    256
#define HEADS   8
#define DHDIM   32
#define BHDIM   128      // BATCH*HEADS
#define NHASH   8
#define NCHUNK  80
#define NROWS   10240    // BATCH*T

// ---------------- scratch (device globals; no allocation allowed) ----------------
__device__ float g_tokens[NROWS*EMBD];
__device__ float g_qk[BHDIM*T*DHDIM];
__device__ float g_v [BHDIM*T*DHDIM];
__device__ int   g_bucket[BHDIM*NHASH*T];
__device__ int   g_sorted[BHDIM*NHASH*T];
__device__ float g_ohash[(size_t)BHDIM*NHASH*T*DHDIM];
__device__ float g_logit[BHDIM*NHASH*T];
__device__ float g_omerged[NROWS*EMBD];
// pre-transposed + pre-split weights: [n][k] layout, hi/lo planes
__device__ float g_wqkT_hi[EMBD*EMBD], g_wqkT_lo[EMBD*EMBD];
__device__ float g_wvT_hi [EMBD*EMBD], g_wvT_lo [EMBD*EMBD];
__device__ float g_woT_hi [EMBD*EMBD], g_woT_lo [EMBD*EMBD];

// ---------------- tf32 mma.sync helpers ----------------
__device__ __forceinline__ void mma_tf32(float* d, const unsigned* a, const unsigned* b){
  asm volatile(
    "mma.sync.aligned.m16n8k8.row.col.f32.tf32.tf32.f32 "
    "{%0,%1,%2,%3}, {%4,%5,%6,%7}, {%8,%9}, {%0,%1,%2,%3};"
    : "+f"(d[0]), "+f"(d[1]), "+f"(d[2]), "+f"(d[3])
    : "r"(a[0]), "r"(a[1]), "r"(a[2]), "r"(a[3]), "r"(b[0]), "r"(b[1]));
}
// cheap split: hi = x with low 13 mantissa bits zeroed (exact tf32 value), lo = x - hi
__device__ __forceinline__ void tf32_split(float x, unsigned &hi, unsigned &lo){
  unsigned hb = __float_as_uint(x) & 0xFFFFE000u;
  hi = hb;
  lo = __float_as_uint(x - __uint_as_float(hb));
}
// round-to-nearest tf32 (zero-mean rounding, used where the lo-term is dropped)
__device__ __forceinline__ unsigned tf32_rna(float x){
  unsigned u; asm("cvt.rna.tf32.f32 %0, %1;" : "=r"(u) : "f"(x)); return u;
}
__device__ __forceinline__ unsigned fu(float x){ return __float_as_uint(x); }

// ---------------- stage 0: weight transpose + split ----------------
__global__ void wsplit_kernel(const float* __restrict__ wqk,
                              const float* __restrict__ wv,
                              const float* __restrict__ wo){
  __shared__ float tile[32][33];
  int z = blockIdx.z;
  const float* src = (z==0) ? wqk : (z==1) ? wv : wo;
  float* dh = (z==0) ? g_wqkT_hi : (z==1) ? g_wvT_hi : g_woT_hi;
  float* dl = (z==0) ? g_wqkT_lo : (z==1) ? g_wvT_lo : g_woT_lo;
  int n0 = blockIdx.x*32, k0 = blockIdx.y*32;
  #pragma unroll
  for (int r=0;r<4;r++){
    int k = threadIdx.y + r*8;
    tile[k][threadIdx.x] = src[(k0+k)*EMBD + n0 + threadIdx.x];
  }
  __syncthreads();
  #pragma unroll
  for (int r=0;r<4;r++){
    int n = threadIdx.y + r*8;
    float v = tile[threadIdx.x][n];
    float hv = __uint_as_float(__float_as_uint(v) & 0xFFFFE000u);
    int oi = (n0+n)*EMBD + k0 + threadIdx.x;
    dh[oi] = hv;
    dl[oi] = v - hv;
  }
}

// ---------------- stage 1: maxpool + Haar DWT -> tokens (smem tiled) ----------------
__global__ __launch_bounds__(256) void frontend_kernel(const float* __restrict__ x){
  __shared__ float s_x[32][33];
  int plane = blockIdx.x;            // b*128 + ch
  int b = plane >> 7, ch = plane & 127;
  const float* xp = x + (size_t)plane*1024;
  int t = threadIdx.x;

  {
    float4 v = *(const float4*)(xp + t*4);
    int r = t >> 3, c4 = (t & 7)*4;
    s_x[r][c4]=v.x; s_x[r][c4+1]=v.y; s_x[r][c4+2]=v.z; s_x[r][c4+3]=v.w;
  }
  __syncthreads();

  int i = t >> 4, j = t & 15;
  float m = -INFINITY;
  int r0 = 2*i-1, c0 = 2*j-1;
  #pragma unroll
  for (int dr=0;dr<3;dr++){
    int r = r0+dr; if (r<0 || r>31) continue;
    #pragma unroll
    for (int dc=0;dc<3;dc++){
      int cc = c0+dc; if (cc<0 || cc>31) continue;
      m = fmaxf(m, s_x[r][cc]);
    }
  }
  float a  = s_x[2*i][2*j];
  float bb = s_x[2*i][2*j+1];
  float c  = s_x[2*i+1][2*j];
  float d  = s_x[2*i+1][2*j+1];
  float ll = (a+bb+c+d)*0.5f;
  float lh = (a-bb+c-d)*0.5f;
  float hl = (a+bb-c-d)*0.5f;
  float hh = (a-bb-c+d)*0.5f;

  size_t rowbase = (size_t)b*640;
  g_tokens[(rowbase + ch      )*256 + t] = m;
  g_tokens[(rowbase + 128 + ch)*256 + t] = ll;
  g_tokens[(rowbase + 256 + ch)*256 + t] = lh;
  g_tokens[(rowbase + 384 + ch)*256 + t] = hl;
  g_tokens[(rowbase + 512 + ch)*256 + t] = hh;
}

// ---------------- stage 2: fused qk/v GEMM, 3xTF32 tensor cores ----------------
#define SMEM_QKV ((128*36 + 4*64*36)*4)

__global__ __launch_bounds__(256) void gemm_qkv_tc(){
  extern __shared__ float sm[];
  float* s_a   = sm;                 // [128][36]
  float* s_b1h = s_a   + 128*36;     // [64][36]
  float* s_b1l = s_b1h + 64*36;
  float* s_b2h = s_b1l + 64*36;
  float* s_b2l = s_b2h + 64*36;

  int tid = threadIdx.x;
  int m0 = blockIdx.y*128, n0 = blockIdx.x*64;
  int warp = tid>>5, lane = tid&31;
  int g = lane>>2, tig = lane&3;
  int rA = warp*16 + g, rB = rA + 8;

  float acc1[8][4], acc2[8][4];
  #pragma unroll
  for (int nt=0;nt<8;nt++)
    #pragma unroll
    for (int u=0;u<4;u++){ acc1[nt][u]=0.f; acc2[nt][u]=0.f; }

  for (int kc=0;kc<EMBD;kc+=32){
    __syncthreads();
    {
      int row = tid>>1, half = (tid&1)*16;
      const float* asrc = g_tokens + (size_t)(m0+row)*EMBD + kc + half;
      #pragma unroll
      for (int u=0;u<16;u+=4)
        *(float4*)&s_a[row*36 + half + u] = *(const float4*)(asrc+u);
    }
    {
      int n = tid>>2, kq = (tid&3)*8;
      size_t bo = (size_t)(n0+n)*EMBD + kc + kq;
      *(float4*)&s_b1h[n*36+kq]   = *(const float4*)&g_wqkT_hi[bo];
      *(float4*)&s_b1h[n*36+kq+4] = *(const float4*)&g_wqkT_hi[bo+4];
      *(float4*)&s_b1l[n*36+kq]   = *(const float4*)&g_wqkT_lo[bo];
      *(float4*)&s_b1l[n*36+kq+4] = *(const float4*)&g_wqkT_lo[bo+4];
      *(float4*)&s_b2h[n*36+kq]   = *(const float4*)&g_wvT_hi[bo];
      *(float4*)&s_b2h[n*36+kq+4] = *(const float4*)&g_wvT_hi[bo+4];
      *(float4*)&s_b2l[n*36+kq]   = *(const float4*)&g_wvT_lo[bo];
      *(float4*)&s_b2l[n*36+kq+4] = *(const float4*)&g_wvT_lo[bo+4];
    }
    __syncthreads();

    #pragma unroll
    for (int kk=0;kk<32;kk+=8){
      unsigned ah[4], al[4];
      tf32_split(s_a[rA*36+kk+tig],   ah[0], al[0]);
      tf32_split(s_a[rB*36+kk+tig],   ah[1], al[1]);
      tf32_split(s_a[rA*36+kk+tig+4], ah[2], al[2]);
      tf32_split(s_a[rB*36+kk+tig+4], ah[3], al[3]);
      #pragma unroll
      for (int nt=0;nt<8;nt++){
        int nr = nt*8 + g;
        unsigned b1h[2] = { fu(s_b1h[nr*36+kk+tig]), fu(s_b1h[nr*36+kk+tig+4]) };
        unsigned b1l[2] = { fu(s_b1l[nr*36+kk+tig]), fu(s_b1l[nr*36+kk+tig+4]) };
        mma_tf32(acc1[nt], ah, b1h);
        mma_tf32(acc1[nt], al, b1h);
        mma_tf32(acc1[nt], ah, b1l);
        unsigned b2h[2] = { fu(s_b2h[nr*36+kk+tig]), fu(s_b2h[nr*36+kk+tig+4]) };
        unsigned b2l[2] = { fu(s_b2l[nr*36+kk+tig]), fu(s_b2l[nr*36+kk+tig+4]) };
        mma_tf32(acc2[nt], ah, b2h);
        mma_tf32(acc2[nt], al, b2h);
        mma_tf32(acc2[nt], ah, b2l);
      }
    }
  }
  int rowA = m0 + rA, rowB = m0 + rB;
  int bA = rowA/640, tokA = rowA - bA*640;
  int bB = rowB/640, tokB = rowB - bB*640;
  #pragma unroll
  for (int nt=0;nt<8;nt++){
    int col = n0 + nt*8 + 2*tig;
    int head = col>>5, dh = col&31;
    size_t oA = ((size_t)(bA*8+head)*640 + tokA)*32 + dh;
    size_t oB = ((size_t)(bB*8+head)*640 + tokB)*32 + dh;
    *(float2*)&g_qk[oA] = make_float2(acc1[nt][0], acc1[nt][1]);
    *(float2*)&g_v [oA] = make_float2(acc2[nt][0], acc2[nt][1]);
    *(float2*)&g_qk[oB] = make_float2(acc1[nt][2], acc1[nt][3]);
    *(float2*)&g_v [oB] = make_float2(acc2[nt][2], acc2[nt][3]);
  }
}

// ---------------- stage 3a: LSH bucket ids — warp-per-hash, 4 pos/thread ----------------
__global__ __launch_bounds__(256) void bucket_kernel(const float* __restrict__ rot){
  __shared__ float s_rot[1280];        // [f=32][h=8][i=5]
  __shared__ float s_q[128][33];
  int bh = blockIdx.x, pos0 = blockIdx.y*128;
  int tid = threadIdx.x;

  for (int i=tid;i<1280;i+=256) s_rot[i]=rot[i];
  {
    int row = tid>>1, fh = (tid&1)*16;
    const float* src = g_qk + ((size_t)bh*640 + pos0 + row)*32 + fh;
    #pragma unroll
    for (int u=0;u<16;u+=4){
      float4 v = *(const float4*)(src+u);
      s_q[row][fh+u]=v.x; s_q[row][fh+u+1]=v.y; s_q[row][fh+u+2]=v.z; s_q[row][fh+u+3]=v.w;
    }
  }
  __syncthreads();

  int h = tid>>5, l = tid&31;
  float r5[4][5];
  #pragma unroll
  for (int k=0;k<4;k++)
    #pragma unroll
    for (int i=0;i<5;i++) r5[k][i]=0.f;

  #pragma unroll 4
  for (int f=0;f<32;f++){
    const float* rp = s_rot + f*40 + h*5;   // warp-uniform -> broadcast
    float w0=rp[0], w1=rp[1], w2=rp[2], w3=rp[3], w4=rp[4];
    #pragma unroll
    for (int k=0;k<4;k++){
      float qf = s_q[l + 32*k][f];
      r5[k][0] += qf*w0; r5[k][1] += qf*w1; r5[k][2] += qf*w2;
      r5[k][3] += qf*w3; r5[k][4] += qf*w4;
    }
  }
  #pragma unroll
  for (int k=0;k<4;k++){
    float best = r5[k][0]; int bi = 0;
    #pragma unroll
    for (int i=1;i<5;i++) if (r5[k][i] > best){ best=r5[k][i]; bi=i; }
    #pragma unroll
    for (int i=0;i<5;i++){ float v = -r5[k][i]; if (v > best){ best=v; bi=5+i; } }
    g_bucket[(size_t)bh*NHASH*T + h*640 + pos0 + l + 32*k] = bi;
  }
}

// ---------------- stage 3b: stable counting sort per (bh, hash) — smem staged ----------------
__global__ __launch_bounds__(320) void sort_kernel(){
  __shared__ int s_bk[640];
  __shared__ int cnt[10], off[10];
  int bhh = blockIdx.x;
  const int* bk = g_bucket + bhh*640;
  for (int i=threadIdx.x;i<640;i+=320) s_bk[i]=bk[i];
  __syncthreads();

  int w = threadIdx.x>>5, lane = threadIdx.x&31;
  int count = 0;
  for (int base=0;base<640;base+=32){
    int bb = s_bk[base+lane];
    unsigned mask = __ballot_sync(0xffffffffu, bb==w);
    count += __popc(mask);
  }
  if (lane==0) cnt[w] = count;
  __syncthreads();
  if (threadIdx.x==0){
    int run=0;
    for (int b=0;b<10;b++){ off[b]=run; run+=cnt[b]; }
  }
  __syncthreads();
  int base_off = off[w]; int run = 0;
  int* out = g_sorted + bhh*640;
  for (int base=0;base<640;base+=32){
    int bb = s_bk[base+lane];
    unsigned mask = __ballot_sync(0xffffffffu, bb==w);
    if (bb==w){
      int slot = base_off + run + __popc(mask & ((1u<<lane)-1u));
      out[slot] = base+lane;
    }
    run += __popc(mask);
  }
}

// ---------------- stage 4: chunked attention, 2xTF32 dots + 1xTF32 PV ----------------
#define Q_PAD 36
#define K_PAD 36
#define V_PAD 40
#define P_PAD 132
#define SMEM_ATTN ((64*P_PAD + 128*V_PAD + 2*128)*4 + (64+128)*4)

__global__ __launch_bounds__(256) void attn_kernel(){
  extern __shared__ char smem_raw[];
  float* s_p    = (float*)smem_raw;          // [64][132]
  float* s_q    = s_p;                       // [64][36]  alias
  float* s_k    = s_p + 64*Q_PAD;            // [128][36] alias
  float* s_v    = s_p + 64*P_PAD;            // [128][40]
  float* s_redm = s_v + 128*V_PAD;           // [2][64]
  float* s_reds = s_redm + 128;              // [2][64]
  int*   s_qt   = (int*)(s_reds + 128);      // [64]
  int*   s_kt   = s_qt + 64;                 // [128]

  int tid = threadIdx.x;
  int blk = blockIdx.x;
  int bh = blk / NCHUNK, c = blk % NCHUNK;
  int h  = c / 10;
  int pc = (c + NCHUNK - 1) % NCHUNK;
  int ph = pc / 10;
  const int* sortedbh = g_sorted + bh*NHASH*T;

  if (tid < 64)
    s_qt[tid] = sortedbh[h*640 + (c%10)*64 + tid];
  else if (tid < 192){
    int j = tid - 64;
    s_kt[j] = (j < 64) ? sortedbh[h*640 + (c%10)*64 + j]
                       : sortedbh[ph*640 + (pc%10)*64 + (j-64)];
  }
  __syncthreads();

  {
    int i = tid >> 2, f0 = (tid & 3) * 8;
    const float* src = g_qk + ((size_t)bh*640 + s_qt[i])*32 + f0;
    *(float4*)&s_q[i*Q_PAD + f0]     = *(const float4*)src;
    *(float4*)&s_q[i*Q_PAD + f0 + 4] = *(const float4*)(src+4);
  }
  {
    int j = tid >> 1, fh = (tid & 1) * 16;
    const float* src = g_qk + ((size_t)bh*640 + s_kt[j])*32 + fh;
    float buf[16]; float ss = 0.f;
    #pragma unroll
    for (int u=0;u<16;u+=4){
      float4 a = *(const float4*)(src+u);
      buf[u]=a.x; buf[u+1]=a.y; buf[u+2]=a.z; buf[u+3]=a.w;
      ss += a.x*a.x + a.y*a.y + a.z*a.z + a.w*a.w;
    }
    ss += __shfl_xor_sync(0xffffffffu, ss, 1);
    float inv = 1.f / fmaxf(sqrtf(ss), 1e-6f);
    #pragma unroll
    for (int u=0;u<16;u+=4)
      *(float4*)&s_k[j*K_PAD + fh + u] =
        make_float4(buf[u]*inv, buf[u+1]*inv, buf[u+2]*inv, buf[u+3]*inv);
  }
  {
    int j = tid >> 1, fh = (tid & 1) * 16;
    const float* src = g_v + ((size_t)bh*640 + s_kt[j])*32 + fh;
    #pragma unroll
    for (int u=0;u<16;u+=4)
      *(float4*)&s_v[j*V_PAD + fh + u] = *(const float4*)(src+u);
  }
  __syncthreads();

  int warp = tid >> 5, lane = tid & 31;
  int wm = warp & 3, wn = warp >> 2;
  int g = lane >> 2, tig = lane & 3;
  int m0 = wm * 16;
  int rA = m0 + g, rB = m0 + g + 8;

  // ---- dots: S(16x64 per warp) = Q x K^T, 2xTF32 (Q exact split, K rna) ----
  float acc[8][4];
  #pragma unroll
  for (int nt=0;nt<8;nt++)
    #pragma unroll
    for (int u=0;u<4;u++) acc[nt][u] = 0.f;

  #pragma unroll
  for (int k0=0;k0<32;k0+=8){
    unsigned ah[4], al[4];
    tf32_split(s_q[rA*Q_PAD + k0 + tig],     ah[0], al[0]);
    tf32_split(s_q[rB*Q_PAD + k0 + tig],     ah[1], al[1]);
    tf32_split(s_q[rA*Q_PAD + k0 + tig + 4], ah[2], al[2]);
    tf32_split(s_q[rB*Q_PAD + k0 + tig + 4], ah[3], al[3]);
    #pragma unroll
    for (int nt=0;nt<8;nt++){
      int n0 = wn*64 + nt*8;
      unsigned bhh[2];
      bhh[0] = tf32_rna(s_k[(n0+g)*K_PAD + k0 + tig]);
      bhh[1] = tf32_rna(s_k[(n0+g)*K_PAD + k0 + tig + 4]);
      mma_tf32(acc[nt], ah, bhh);
      mma_tf32(acc[nt], al, bhh);
    }
  }

  int qtA = s_qt[rA], qtB = s_qt[rB];
  #pragma unroll
  for (int nt=0;nt<8;nt++){
    int n0 = wn*64 + nt*8;
    int kt0 = s_kt[n0 + 2*tig], kt1 = s_kt[n0 + 2*tig + 1];
    acc[nt][0] = (kt0==qtA) ? -50000.f : acc[nt][0]*0.17677669529663687f;
    acc[nt][1] = (kt1==qtA) ? -50000.f : acc[nt][1]*0.17677669529663687f;
    acc[nt][2] = (kt0==qtB) ? -50000.f : acc[nt][2]*0.17677669529663687f;
    acc[nt][3] = (kt1==qtB) ? -50000.f : acc[nt][3]*0.17677669529663687f;
  }

  float mA=-INFINITY, mB=-INFINITY;
  #pragma unroll
  for (int nt=0;nt<8;nt++){
    mA = fmaxf(mA, fmaxf(acc[nt][0], acc[nt][1]));
    mB = fmaxf(mB, fmaxf(acc[nt][2], acc[nt][3]));
  }
  #pragma unroll
  for (int o=1;o<=2;o<<=1){
    mA = fmaxf(mA, __shfl_xor_sync(0xffffffffu, mA, o, 4));
    mB = fmaxf(mB, __shfl_xor_sync(0xffffffffu, mB, o, 4));
  }
  float sA=0.f, sB=0.f;
  #pragma unroll
  for (int nt=0;nt<8;nt++){
    acc[nt][0] = __expf(acc[nt][0]-mA);
    acc[nt][1] = __expf(acc[nt][1]-mA);
    acc[nt][2] = __expf(acc[nt][2]-mB);
    acc[nt][3] = __expf(acc[nt][3]-mB);
    sA += acc[nt][0] + acc[nt][1];
    sB += acc[nt][2] + acc[nt][3];
  }
  #pragma unroll
  for (int o=1;o<=2;o<<=1){
    sA += __shfl_xor_sync(0xffffffffu, sA, o, 4);
    sB += __shfl_xor_sync(0xffffffffu, sB, o, 4);
  }
  if (tig == 0){
    s_redm[wn*64 + rA] = mA;  s_reds[wn*64 + rA] = sA;
    s_redm[wn*64 + rB] = mB;  s_reds[wn*64 + rB] = sB;
  }
  __syncthreads();

  float lseA, lseB;
  {
    float m0A = s_redm[rA], m1A = s_redm[64+rA];
    float mm = fmaxf(m0A, m1A);
    float ss = s_reds[rA]*__expf(m0A-mm) + s_reds[64+rA]*__expf(m1A-mm);
    lseA = mm + __logf(ss);
    float m0B = s_redm[rB], m1B = s_redm[64+rB];
    mm = fmaxf(m0B, m1B);
    ss = s_reds[rB]*__expf(m0B-mm) + s_reds[64+rB]*__expf(m1B-mm);
    lseB = mm + __logf(ss);
  }
  if (wn == 0 && tig == 0){
    g_logit[(bh*NHASH+h)*T + qtA] = lseA;
    g_logit[(bh*NHASH+h)*T + qtB] = lseB;
  }

  float scA = __expf(mA - lseA);
  float scB = __expf(mB - lseB);
  #pragma unroll
  for (int nt=0;nt<8;nt++){
    int n0 = wn*64 + nt*8;
    *(float2*)&s_p[rA*P_PAD + n0 + 2*tig] =
      make_float2(acc[nt][0]*scA, acc[nt][1]*scA);
    *(float2*)&s_p[rB*P_PAD + n0 + 2*tig] =
      make_float2(acc[nt][2]*scB, acc[nt][3]*scB);
  }
  __syncthreads();

  // ---- PV: pure 1xTF32 (probs + V via rna) ----
  float o0[4] = {0.f,0.f,0.f,0.f};
  float o1[4] = {0.f,0.f,0.f,0.f};
  int d0 = wn*16;
  #pragma unroll 2
  for (int k0=0;k0<128;k0+=8){
    unsigned ap[4];
    ap[0] = tf32_rna(s_p[rA*P_PAD + k0 + tig]);
    ap[1] = tf32_rna(s_p[rB*P_PAD + k0 + tig]);
    ap[2] = tf32_rna(s_p[rA*P_PAD + k0 + tig + 4]);
    ap[3] = tf32_rna(s_p[rB*P_PAD + k0 + tig + 4]);
    unsigned b0h[2], b1h[2];
    b0h[0] = tf32_rna(s_v[(k0+tig)*V_PAD   + d0 + g]);
    b0h[1] = tf32_rna(s_v[(k0+tig+4)*V_PAD + d0 + g]);
    b1h[0] = tf32_rna(s_v[(k0+tig)*V_PAD   + d0 + 8 + g]);
    b1h[1] = tf32_rna(s_v[(k0+tig+4)*V_PAD + d0 + 8 + g]);
    mma_tf32(o0, ap, b0h);
    mma_tf32(o1, ap, b1h);
  }
  {
    size_t base = (size_t)(bh*NHASH+h)*T;
    float* dA = g_ohash + (base + qtA)*32;
    float* dB = g_ohash + (base + qtB)*32;
    *(float2*)(dA + d0 + 2*tig)     = make_float2(o0[0], o0[1]);
    *(float2*)(dB + d0 + 2*tig)     = make_float2(o0[2], o0[3]);
    *(float2*)(dA + d0 + 8 + 2*tig) = make_float2(o1[0], o1[1]);
    *(float2*)(dB + d0 + 8 + 2*tig) = make_float2(o1[2], o1[3]);
  }
}

// ---------------- stage 5: combine hashes, merge heads (float4) ----------------
__global__ void combine_kernel(){
  int idx = blockIdx.x*blockDim.x + threadIdx.x;
  if (idx >= BHDIM*T*8) return;
  int dq  = idx & 7;
  int pos = (idx >> 3) % 640;
  int bh  = idx / (640*8);
  float l[NHASH];
  #pragma unroll
  for (int h=0;h<NHASH;h++) l[h] = g_logit[(bh*NHASH+h)*T + pos];
  float m = l[0];
  #pragma unroll
  for (int h=1;h<NHASH;h++) m = fmaxf(m, l[h]);
  float s = 0.f;
  float e[NHASH];
  #pragma unroll
  for (int h=0;h<NHASH;h++){ e[h] = __expf(l[h]-m); s += e[h]; }
  float inv = 1.f/s;
  float4 acc = make_float4(0.f,0.f,0.f,0.f);
  #pragma unroll
  for (int h=0;h<NHASH;h++){
    float w = e[h]*inv;
    float4 v = *(const float4*)(g_ohash + ((size_t)(bh*NHASH+h)*T + pos)*32 + dq*4);
    acc.x += w*v.x; acc.y += w*v.y; acc.z += w*v.z; acc.w += w*v.w;
  }
  int b = bh>>3, head = bh&7;
  *(float4*)(g_omerged + ((size_t)b*640 + pos)*256 + head*32 + dq*4) = acc;
}

// ---------------- stage 6: output GEMM + bias, 3xTF32 tensor cores ----------------
__global__ __launch_bounds__(256) void gemm_out_tc(const float* __restrict__ bias,
                                                   float* __restrict__ out){
  __shared__ float s_a[128*36];
  __shared__ float s_bh[64*36];
  __shared__ float s_bl[64*36];

  int tid = threadIdx.x;
  int m0 = blockIdx.y*128, n0 = blockIdx.x*64;
  int warp = tid>>5, lane = tid&31;
  int g = lane>>2, tig = lane&3;
  int rA = warp*16 + g, rB = rA + 8;

  float acc[8][4];
  #pragma unroll
  for (int nt=0;nt<8;nt++)
    #pragma unroll
    for (int u=0;u<4;u++) acc[nt][u]=0.f;

  for (int kc=0;kc<EMBD;kc+=32){
    __syncthreads();
    {
      int row = tid>>1, half = (tid&1)*16;
      const float* asrc = g_omerged + (size_t)(m0+row)*EMBD + kc + half;
      #pragma unroll
      for (int u=0;u<16;u+=4)
        *(float4*)&s_a[row*36 + half + u] = *(const float4*)(asrc+u);
    }
    {
      int n = tid>>2, kq = (tid&3)*8;
      size_t bo = (size_t)(n0+n)*EMBD + kc + kq;
      *(float4*)&s_bh[n*36+kq]   = *(const float4*)&g_woT_hi[bo];
      *(float4*)&s_bh[n*36+kq+4] = *(const float4*)&g_woT_hi[bo+4];
      *(float4*)&s_bl[n*36+kq]   = *(const float4*)&g_woT_lo[bo];
      *(float4*)&s_bl[n*36+kq+4] = *(const float4*)&g_woT_lo[bo+4];
    }
    __syncthreads();

    #pragma unroll
    for (int kk=0;kk<32;kk+=8){
      unsigned ah[4], al[4];
      tf32_split(s_a[rA*36+kk+tig],   ah[0], al[0]);
      tf32_split(s_a[rB*36+kk+tig],   ah[1], al[1]);
      tf32_split(s_a[rA*36+kk+tig+4], ah[2], al[2]);
      tf32_split(s_a[rB*36+kk+tig+4], ah[3], al[3]);
      #pragma unroll
      for (int nt=0;nt<8;nt++){
        int nr = nt*8 + g;
        unsigned bhv[2] = { fu(s_bh[nr*36+kk+tig]), fu(s_bh[nr*36+kk+tig+4]) };
        unsigned blv[2] = { fu(s_bl[nr*36+kk+tig]), fu(s_bl[nr*36+kk+tig+4]) };
        mma_tf32(acc[nt], ah, bhv);
        mma_tf32(acc[nt], al, bhv);
        mma_tf32(acc[nt], ah, blv);
      }
    }
  }
  int rowA = m0 + rA, rowB = m0 + rB;
  #pragma unroll
  for (int nt=0;nt<8;nt++){
    int col = n0 + nt*8 + 2*tig;
    float b0 = __ldg(bias+col), b1 = __ldg(bias+col+1);
    *(float2*)&out[(size_t)rowA*EMBD + col] = make_float2(acc[nt][0]+b0, acc[nt][1]+b1);
    *(float2*)&out[(size_t)rowB*EMBD + col] = make_float2(acc[nt][2]+b0, acc[nt][3]+b1);
  }
}

// ---------------- launch ----------------
extern "C" void kernel_launch(void* const* d_in, const int* in_sizes, int n_in,
                              void* d_out, int out_size){
  const float* x     = (const float*)d_in[0];
  const float* w_qk  = (const float*)d_in[1];
  const float* w_v   = (const float*)d_in[2];
  const float* w_out = (const float*)d_in[3];
  const float* b_out = (const float*)d_in[4];
  const float* rot   = (const float*)d_in[5];
  float* out = (float*)d_out;

  wsplit_kernel<<<dim3(8,8,3), dim3(32,8)>>>(w_qk, w_v, w_out);
  frontend_kernel<<<BATCH*128, 256>>>(x);
  cudaFuncSetAttribute(gemm_qkv_tc, cudaFuncAttributeMaxDynamicSharedMemorySize, SMEM_QKV);
  gemm_qkv_tc<<<dim3(4,80), 256, SMEM_QKV>>>();
  bucket_kernel<<<dim3(BHDIM, T/128), 256>>>(rot);
  sort_kernel<<<BHDIM*NHASH, 320>>>();
  cudaFuncSetAttribute(attn_kernel, cudaFuncAttributeMaxDynamicSharedMemorySize, SMEM_ATTN);
  attn_kernel<<<BHDIM*NCHUNK, 256, SMEM_ATTN>>>();
  combine_kernel<<<(BHDIM*T*8+255)/256, 256>>>();
  gemm_out_tc<<<dim3(4,80), 256>>>(b_out, out);
}

// round 15
// speedup vs baseline: 1.2260x; 1.0595x over previous
#include <cuda_runtime.h>
#include <math.h>

#define BATCH   16
#define T       640
#define EMBD    256
#define HEADS   8
#define DHDIM   32
#define BHDIM   128      // BATCH*HEADS
#define NHASH   8
#define NCHUNK  80
#define NROWS   10240    // BATCH*T

// ---------------- scratch (device globals; no allocation allowed) ----------------
__device__ float g_tokens[NROWS*EMBD];
__device__ float g_qk[BHDIM*T*DHDIM];
__device__ float g_v [BHDIM*T*DHDIM];
__device__ int   g_bucket[BHDIM*NHASH*T];
__device__ int   g_sorted[BHDIM*NHASH*T];
__device__ float g_ohash[(size_t)BHDIM*NHASH*T*DHDIM];
__device__ float g_logit[BHDIM*NHASH*T];
__device__ float g_omerged[NROWS*EMBD];
// pre-transposed + pre-split weights: [n][k] layout, hi/lo planes
__device__ float g_wqkT_hi[EMBD*EMBD], g_wqkT_lo[EMBD*EMBD];
__device__ float g_wvT_hi [EMBD*EMBD], g_wvT_lo [EMBD*EMBD];
__device__ float g_woT_hi [EMBD*EMBD], g_woT_lo [EMBD*EMBD];

// ---------------- tf32 mma.sync helpers ----------------
__device__ __forceinline__ void mma_tf32(float* d, const unsigned* a, const unsigned* b){
  asm volatile(
    "mma.sync.aligned.m16n8k8.row.col.f32.tf32.tf32.f32 "
    "{%0,%1,%2,%3}, {%4,%5,%6,%7}, {%8,%9}, {%0,%1,%2,%3};"
    : "+f"(d[0]), "+f"(d[1]), "+f"(d[2]), "+f"(d[3])
    : "r"(a[0]), "r"(a[1]), "r"(a[2]), "r"(a[3]), "r"(b[0]), "r"(b[1]));
}
// cheap split: hi = x with low 13 mantissa bits zeroed (exact tf32 value), lo = x - hi
__device__ __forceinline__ void tf32_split(float x, unsigned &hi, unsigned &lo){
  unsigned hb = __float_as_uint(x) & 0xFFFFE000u;
  hi = hb;
  lo = __float_as_uint(x - __uint_as_float(hb));
}
// round-to-nearest tf32 (zero-mean rounding, used where the lo-term is dropped)
__device__ __forceinline__ unsigned tf32_rna(float x){
  unsigned u; asm("cvt.rna.tf32.f32 %0, %1;" : "=r"(u) : "f"(x)); return u;
}
__device__ __forceinline__ unsigned fu(float x){ return __float_as_uint(x); }

// ---------------- stage 0: weight transpose + split ----------------
// z==0,1 (wqk, wv): truncation hi/lo planes (exact 3xTF32 path)
// z==2   (wo):      hi = rna-rounded single plane (2xTF32 path), lo unused
__global__ void wsplit_kernel(const float* __restrict__ wqk,
                              const float* __restrict__ wv,
                              const float* __restrict__ wo){
  __shared__ float tile[32][33];
  int z = blockIdx.z;
  const float* src = (z==0) ? wqk : (z==1) ? wv : wo;
  float* dh = (z==0) ? g_wqkT_hi : (z==1) ? g_wvT_hi : g_woT_hi;
  float* dl = (z==0) ? g_wqkT_lo : (z==1) ? g_wvT_lo : g_woT_lo;
  int n0 = blockIdx.x*32, k0 = blockIdx.y*32;
  #pragma unroll
  for (int r=0;r<4;r++){
    int k = threadIdx.y + r*8;
    tile[k][threadIdx.x] = src[(k0+k)*EMBD + n0 + threadIdx.x];
  }
  __syncthreads();
  #pragma unroll
  for (int r=0;r<4;r++){
    int n = threadIdx.y + r*8;
    float v = tile[threadIdx.x][n];
    int oi = (n0+n)*EMBD + k0 + threadIdx.x;
    if (z == 2){
      dh[oi] = __uint_as_float(tf32_rna(v));
      dl[oi] = 0.f;
    } else {
      float hv = __uint_as_float(__float_as_uint(v) & 0xFFFFE000u);
      dh[oi] = hv;
      dl[oi] = v - hv;
    }
  }
}

// ---------------- stage 1: maxpool + Haar DWT -> tokens (smem tiled) ----------------
__global__ __launch_bounds__(256) void frontend_kernel(const float* __restrict__ x){
  __shared__ float s_x[32][33];
  int plane = blockIdx.x;            // b*128 + ch
  int b = plane >> 7, ch = plane & 127;
  const float* xp = x + (size_t)plane*1024;
  int t = threadIdx.x;

  {
    float4 v = *(const float4*)(xp + t*4);
    int r = t >> 3, c4 = (t & 7)*4;
    s_x[r][c4]=v.x; s_x[r][c4+1]=v.y; s_x[r][c4+2]=v.z; s_x[r][c4+3]=v.w;
  }
  __syncthreads();

  int i = t >> 4, j = t & 15;
  float m = -INFINITY;
  int r0 = 2*i-1, c0 = 2*j-1;
  #pragma unroll
  for (int dr=0;dr<3;dr++){
    int r = r0+dr; if (r<0 || r>31) continue;
    #pragma unroll
    for (int dc=0;dc<3;dc++){
      int cc = c0+dc; if (cc<0 || cc>31) continue;
      m = fmaxf(m, s_x[r][cc]);
    }
  }
  float a  = s_x[2*i][2*j];
  float bb = s_x[2*i][2*j+1];
  float c  = s_x[2*i+1][2*j];
  float d  = s_x[2*i+1][2*j+1];
  float ll = (a+bb+c+d)*0.5f;
  float lh = (a-bb+c-d)*0.5f;
  float hl = (a+bb-c-d)*0.5f;
  float hh = (a-bb-c+d)*0.5f;

  size_t rowbase = (size_t)b*640;
  g_tokens[(rowbase + ch      )*256 + t] = m;
  g_tokens[(rowbase + 128 + ch)*256 + t] = ll;
  g_tokens[(rowbase + 256 + ch)*256 + t] = lh;
  g_tokens[(rowbase + 384 + ch)*256 + t] = hl;
  g_tokens[(rowbase + 512 + ch)*256 + t] = hh;
}

// ---------------- stage 2: fused qk/v GEMM, 3xTF32 tensor cores ----------------
#define SMEM_QKV ((128*36 + 4*64*36)*4)

__global__ __launch_bounds__(256) void gemm_qkv_tc(){
  extern __shared__ float sm[];
  float* s_a   = sm;                 // [128][36]
  float* s_b1h = s_a   + 128*36;     // [64][36]
  float* s_b1l = s_b1h + 64*36;
  float* s_b2h = s_b1l + 64*36;
  float* s_b2l = s_b2h + 64*36;

  int tid = threadIdx.x;
  int m0 = blockIdx.y*128, n0 = blockIdx.x*64;
  int warp = tid>>5, lane = tid&31;
  int g = lane>>2, tig = lane&3;
  int rA = warp*16 + g, rB = rA + 8;

  float acc1[8][4], acc2[8][4];
  #pragma unroll
  for (int nt=0;nt<8;nt++)
    #pragma unroll
    for (int u=0;u<4;u++){ acc1[nt][u]=0.f; acc2[nt][u]=0.f; }

  for (int kc=0;kc<EMBD;kc+=32){
    __syncthreads();
    {
      int row = tid>>1, half = (tid&1)*16;
      const float* asrc = g_tokens + (size_t)(m0+row)*EMBD + kc + half;
      #pragma unroll
      for (int u=0;u<16;u+=4)
        *(float4*)&s_a[row*36 + half + u] = *(const float4*)(asrc+u);
    }
    {
      int n = tid>>2, kq = (tid&3)*8;
      size_t bo = (size_t)(n0+n)*EMBD + kc + kq;
      *(float4*)&s_b1h[n*36+kq]   = *(const float4*)&g_wqkT_hi[bo];
      *(float4*)&s_b1h[n*36+kq+4] = *(const float4*)&g_wqkT_hi[bo+4];
      *(float4*)&s_b1l[n*36+kq]   = *(const float4*)&g_wqkT_lo[bo];
      *(float4*)&s_b1l[n*36+kq+4] = *(const float4*)&g_wqkT_lo[bo+4];
      *(float4*)&s_b2h[n*36+kq]   = *(const float4*)&g_wvT_hi[bo];
      *(float4*)&s_b2h[n*36+kq+4] = *(const float4*)&g_wvT_hi[bo+4];
      *(float4*)&s_b2l[n*36+kq]   = *(const float4*)&g_wvT_lo[bo];
      *(float4*)&s_b2l[n*36+kq+4] = *(const float4*)&g_wvT_lo[bo+4];
    }
    __syncthreads();

    #pragma unroll
    for (int kk=0;kk<32;kk+=8){
      unsigned ah[4], al[4];
      tf32_split(s_a[rA*36+kk+tig],   ah[0], al[0]);
      tf32_split(s_a[rB*36+kk+tig],   ah[1], al[1]);
      tf32_split(s_a[rA*36+kk+tig+4], ah[2], al[2]);
      tf32_split(s_a[rB*36+kk+tig+4], ah[3], al[3]);
      #pragma unroll
      for (int nt=0;nt<8;nt++){
        int nr = nt*8 + g;
        unsigned b1h[2] = { fu(s_b1h[nr*36+kk+tig]), fu(s_b1h[nr*36+kk+tig+4]) };
        unsigned b1l[2] = { fu(s_b1l[nr*36+kk+tig]), fu(s_b1l[nr*36+kk+tig+4]) };
        mma_tf32(acc1[nt], ah, b1h);
        mma_tf32(acc1[nt], al, b1h);
        mma_tf32(acc1[nt], ah, b1l);
        unsigned b2h[2] = { fu(s_b2h[nr*36+kk+tig]), fu(s_b2h[nr*36+kk+tig+4]) };
        unsigned b2l[2] = { fu(s_b2l[nr*36+kk+tig]), fu(s_b2l[nr*36+kk+tig+4]) };
        mma_tf32(acc2[nt], ah, b2h);
        mma_tf32(acc2[nt], al, b2h);
        mma_tf32(acc2[nt], ah, b2l);
      }
    }
  }
  int rowA = m0 + rA, rowB = m0 + rB;
  int bA = rowA/640, tokA = rowA - bA*640;
  int bB = rowB/640, tokB = rowB - bB*640;
  #pragma unroll
  for (int nt=0;nt<8;nt++){
    int col = n0 + nt*8 + 2*tig;
    int head = col>>5, dh = col&31;
    size_t oA = ((size_t)(bA*8+head)*640 + tokA)*32 + dh;
    size_t oB = ((size_t)(bB*8+head)*640 + tokB)*32 + dh;
    *(float2*)&g_qk[oA] = make_float2(acc1[nt][0], acc1[nt][1]);
    *(float2*)&g_v [oA] = make_float2(acc2[nt][0], acc2[nt][1]);
    *(float2*)&g_qk[oB] = make_float2(acc1[nt][2], acc1[nt][3]);
    *(float2*)&g_v [oB] = make_float2(acc2[nt][2], acc2[nt][3]);
  }
}

// ---------------- stage 3a: LSH bucket ids — warp-per-hash, 4 pos/thread ----------------
__global__ __launch_bounds__(256) void bucket_kernel(const float* __restrict__ rot){
  __shared__ float s_rot[1280];        // [f=32][h=8][i=5]
  __shared__ float s_q[128][33];
  int bh = blockIdx.x, pos0 = blockIdx.y*128;
  int tid = threadIdx.x;

  for (int i=tid;i<1280;i+=256) s_rot[i]=rot[i];
  {
    int row = tid>>1, fh = (tid&1)*16;
    const float* src = g_qk + ((size_t)bh*640 + pos0 + row)*32 + fh;
    #pragma unroll
    for (int u=0;u<16;u+=4){
      float4 v = *(const float4*)(src+u);
      s_q[row][fh+u]=v.x; s_q[row][fh+u+1]=v.y; s_q[row][fh+u+2]=v.z; s_q[row][fh+u+3]=v.w;
    }
  }
  __syncthreads();

  int h = tid>>5, l = tid&31;
  float r5[4][5];
  #pragma unroll
  for (int k=0;k<4;k++)
    #pragma unroll
    for (int i=0;i<5;i++) r5[k][i]=0.f;

  #pragma unroll 4
  for (int f=0;f<32;f++){
    const float* rp = s_rot + f*40 + h*5;   // warp-uniform -> broadcast
    float w0=rp[0], w1=rp[1], w2=rp[2], w3=rp[3], w4=rp[4];
    #pragma unroll
    for (int k=0;k<4;k++){
      float qf = s_q[l + 32*k][f];
      r5[k][0] += qf*w0; r5[k][1] += qf*w1; r5[k][2] += qf*w2;
      r5[k][3] += qf*w3; r5[k][4] += qf*w4;
    }
  }
  #pragma unroll
  for (int k=0;k<4;k++){
    float best = r5[k][0]; int bi = 0;
    #pragma unroll
    for (int i=1;i<5;i++) if (r5[k][i] > best){ best=r5[k][i]; bi=i; }
    #pragma unroll
    for (int i=0;i<5;i++){ float v = -r5[k][i]; if (v > best){ best=v; bi=5+i; } }
    g_bucket[(size_t)bh*NHASH*T + h*640 + pos0 + l + 32*k] = bi;
  }
}

// ---------------- stage 3b: stable counting sort per (bh, hash) — smem staged ----------------
__global__ __launch_bounds__(320) void sort_kernel(){
  __shared__ int s_bk[640];
  __shared__ int cnt[10], off[10];
  int bhh = blockIdx.x;
  const int* bk = g_bucket + bhh*640;
  for (int i=threadIdx.x;i<640;i+=320) s_bk[i]=bk[i];
  __syncthreads();

  int w = threadIdx.x>>5, lane = threadIdx.x&31;
  int count = 0;
  for (int base=0;base<640;base+=32){
    int bb = s_bk[base+lane];
    unsigned mask = __ballot_sync(0xffffffffu, bb==w);
    count += __popc(mask);
  }
  if (lane==0) cnt[w] = count;
  __syncthreads();
  if (threadIdx.x==0){
    int run=0;
    for (int b=0;b<10;b++){ off[b]=run; run+=cnt[b]; }
  }
  __syncthreads();
  int base_off = off[w]; int run = 0;
  int* out = g_sorted + bhh*640;
  for (int base=0;base<640;base+=32){
    int bb = s_bk[base+lane];
    unsigned mask = __ballot_sync(0xffffffffu, bb==w);
    if (bb==w){
      int slot = base_off + run + __popc(mask & ((1u<<lane)-1u));
      out[slot] = base+lane;
    }
    run += __popc(mask);
  }
}

// ---------------- stage 4: chunked attention, 1xTF32 dots + 1xTF32 PV ----------------
#define Q_PAD 36
#define K_PAD 36
#define V_PAD 40
#define P_PAD 132
#define SMEM_ATTN ((64*P_PAD + 128*V_PAD + 2*128)*4 + (64+128)*4)

__global__ __launch_bounds__(256) void attn_kernel(){
  extern __shared__ char smem_raw[];
  float* s_p    = (float*)smem_raw;          // [64][132]
  float* s_q    = s_p;                       // [64][36]  alias
  float* s_k    = s_p + 64*Q_PAD;            // [128][36] alias
  float* s_v    = s_p + 64*P_PAD;            // [128][40]
  float* s_redm = s_v + 128*V_PAD;           // [2][64]
  float* s_reds = s_redm + 128;              // [2][64]
  int*   s_qt   = (int*)(s_reds + 128);      // [64]
  int*   s_kt   = s_qt + 64;                 // [128]

  int tid = threadIdx.x;
  int blk = blockIdx.x;
  int bh = blk / NCHUNK, c = blk % NCHUNK;
  int h  = c / 10;
  int pc = (c + NCHUNK - 1) % NCHUNK;
  int ph = pc / 10;
  const int* sortedbh = g_sorted + bh*NHASH*T;

  if (tid < 64)
    s_qt[tid] = sortedbh[h*640 + (c%10)*64 + tid];
  else if (tid < 192){
    int j = tid - 64;
    s_kt[j] = (j < 64) ? sortedbh[h*640 + (c%10)*64 + j]
                       : sortedbh[ph*640 + (pc%10)*64 + (j-64)];
  }
  __syncthreads();

  {
    int i = tid >> 2, f0 = (tid & 3) * 8;
    const float* src = g_qk + ((size_t)bh*640 + s_qt[i])*32 + f0;
    *(float4*)&s_q[i*Q_PAD + f0]     = *(const float4*)src;
    *(float4*)&s_q[i*Q_PAD + f0 + 4] = *(const float4*)(src+4);
  }
  {
    int j = tid >> 1, fh = (tid & 1) * 16;
    const float* src = g_qk + ((size_t)bh*640 + s_kt[j])*32 + fh;
    float buf[16]; float ss = 0.f;
    #pragma unroll
    for (int u=0;u<16;u+=4){
      float4 a = *(const float4*)(src+u);
      buf[u]=a.x; buf[u+1]=a.y; buf[u+2]=a.z; buf[u+3]=a.w;
      ss += a.x*a.x + a.y*a.y + a.z*a.z + a.w*a.w;
    }
    ss += __shfl_xor_sync(0xffffffffu, ss, 1);
    float inv = 1.f / fmaxf(sqrtf(ss), 1e-6f);
    #pragma unroll
    for (int u=0;u<16;u+=4)
      *(float4*)&s_k[j*K_PAD + fh + u] =
        make_float4(buf[u]*inv, buf[u+1]*inv, buf[u+2]*inv, buf[u+3]*inv);
  }
  {
    int j = tid >> 1, fh = (tid & 1) * 16;
    const float* src = g_v + ((size_t)bh*640 + s_kt[j])*32 + fh;
    #pragma unroll
    for (int u=0;u<16;u+=4)
      *(float4*)&s_v[j*V_PAD + fh + u] = *(const float4*)(src+u);
  }
  __syncthreads();

  int warp = tid >> 5, lane = tid & 31;
  int wm = warp & 3, wn = warp >> 2;
  int g = lane >> 2, tig = lane & 3;
  int m0 = wm * 16;
  int rA = m0 + g, rB = m0 + g + 8;

  // ---- dots: S(16x64 per warp) = Q x K^T, pure 1xTF32 (rna both) ----
  float acc[8][4];
  #pragma unroll
  for (int nt=0;nt<8;nt++)
    #pragma unroll
    for (int u=0;u<4;u++) acc[nt][u] = 0.f;

  #pragma unroll
  for (int k0=0;k0<32;k0+=8){
    unsigned aq[4];
    aq[0] = tf32_rna(s_q[rA*Q_PAD + k0 + tig]);
    aq[1] = tf32_rna(s_q[rB*Q_PAD + k0 + tig]);
    aq[2] = tf32_rna(s_q[rA*Q_PAD + k0 + tig + 4]);
    aq[3] = tf32_rna(s_q[rB*Q_PAD + k0 + tig + 4]);
    #pragma unroll
    for (int nt=0;nt<8;nt++){
      int n0 = wn*64 + nt*8;
      unsigned bhh[2];
      bhh[0] = tf32_rna(s_k[(n0+g)*K_PAD + k0 + tig]);
      bhh[1] = tf32_rna(s_k[(n0+g)*K_PAD + k0 + tig + 4]);
      mma_tf32(acc[nt], aq, bhh);
    }
  }

  int qtA = s_qt[rA], qtB = s_qt[rB];
  #pragma unroll
  for (int nt=0;nt<8;nt++){
    int n0 = wn*64 + nt*8;
    int kt0 = s_kt[n0 + 2*tig], kt1 = s_kt[n0 + 2*tig + 1];
    acc[nt][0] = (kt0==qtA) ? -50000.f : acc[nt][0]*0.17677669529663687f;
    acc[nt][1] = (kt1==qtA) ? -50000.f : acc[nt][1]*0.17677669529663687f;
    acc[nt][2] = (kt0==qtB) ? -50000.f : acc[nt][2]*0.17677669529663687f;
    acc[nt][3] = (kt1==qtB) ? -50000.f : acc[nt][3]*0.17677669529663687f;
  }

  float mA=-INFINITY, mB=-INFINITY;
  #pragma unroll
  for (int nt=0;nt<8;nt++){
    mA = fmaxf(mA, fmaxf(acc[nt][0], acc[nt][1]));
    mB = fmaxf(mB, fmaxf(acc[nt][2], acc[nt][3]));
  }
  #pragma unroll
  for (int o=1;o<=2;o<<=1){
    mA = fmaxf(mA, __shfl_xor_sync(0xffffffffu, mA, o, 4));
    mB = fmaxf(mB, __shfl_xor_sync(0xffffffffu, mB, o, 4));
  }
  float sA=0.f, sB=0.f;
  #pragma unroll
  for (int nt=0;nt<8;nt++){
    acc[nt][0] = __expf(acc[nt][0]-mA);
    acc[nt][1] = __expf(acc[nt][1]-mA);
    acc[nt][2] = __expf(acc[nt][2]-mB);
    acc[nt][3] = __expf(acc[nt][3]-mB);
    sA += acc[nt][0] + acc[nt][1];
    sB += acc[nt][2] + acc[nt][3];
  }
  #pragma unroll
  for (int o=1;o<=2;o<<=1){
    sA += __shfl_xor_sync(0xffffffffu, sA, o, 4);
    sB += __shfl_xor_sync(0xffffffffu, sB, o, 4);
  }
  if (tig == 0){
    s_redm[wn*64 + rA] = mA;  s_reds[wn*64 + rA] = sA;
    s_redm[wn*64 + rB] = mB;  s_reds[wn*64 + rB] = sB;
  }
  __syncthreads();

  float lseA, lseB;
  {
    float m0A = s_redm[rA], m1A = s_redm[64+rA];
    float mm = fmaxf(m0A, m1A);
    float ss = s_reds[rA]*__expf(m0A-mm) + s_reds[64+rA]*__expf(m1A-mm);
    lseA = mm + __logf(ss);
    float m0B = s_redm[rB], m1B = s_redm[64+rB];
    mm = fmaxf(m0B, m1B);
    ss = s_reds[rB]*__expf(m0B-mm) + s_reds[64+rB]*__expf(m1B-mm);
    lseB = mm + __logf(ss);
  }
  if (wn == 0 && tig == 0){
    g_logit[(bh*NHASH+h)*T + qtA] = lseA;
    g_logit[(bh*NHASH+h)*T + qtB] = lseB;
  }

  float scA = __expf(mA - lseA);
  float scB = __expf(mB - lseB);
  #pragma unroll
  for (int nt=0;nt<8;nt++){
    int n0 = wn*64 + nt*8;
    *(float2*)&s_p[rA*P_PAD + n0 + 2*tig] =
      make_float2(acc[nt][0]*scA, acc[nt][1]*scA);
    *(float2*)&s_p[rB*P_PAD + n0 + 2*tig] =
      make_float2(acc[nt][2]*scB, acc[nt][3]*scB);
  }
  __syncthreads();

  // ---- PV: pure 1xTF32 (probs + V via rna) ----
  float o0[4] = {0.f,0.f,0.f,0.f};
  float o1[4] = {0.f,0.f,0.f,0.f};
  int d0 = wn*16;
  #pragma unroll 2
  for (int k0=0;k0<128;k0+=8){
    unsigned ap[4];
    ap[0] = tf32_rna(s_p[rA*P_PAD + k0 + tig]);
    ap[1] = tf32_rna(s_p[rB*P_PAD + k0 + tig]);
    ap[2] = tf32_rna(s_p[rA*P_PAD + k0 + tig + 4]);
    ap[3] = tf32_rna(s_p[rB*P_PAD + k0 + tig + 4]);
    unsigned b0h[2], b1h[2];
    b0h[0] = tf32_rna(s_v[(k0+tig)*V_PAD   + d0 + g]);
    b0h[1] = tf32_rna(s_v[(k0+tig+4)*V_PAD + d0 + g]);
    b1h[0] = tf32_rna(s_v[(k0+tig)*V_PAD   + d0 + 8 + g]);
    b1h[1] = tf32_rna(s_v[(k0+tig+4)*V_PAD + d0 + 8 + g]);
    mma_tf32(o0, ap, b0h);
    mma_tf32(o1, ap, b1h);
  }
  {
    size_t base = (size_t)(bh*NHASH+h)*T;
    float* dA = g_ohash + (base + qtA)*32;
    float* dB = g_ohash + (base + qtB)*32;
    *(float2*)(dA + d0 + 2*tig)     = make_float2(o0[0], o0[1]);
    *(float2*)(dB + d0 + 2*tig)     = make_float2(o0[2], o0[3]);
    *(float2*)(dA + d0 + 8 + 2*tig) = make_float2(o1[0], o1[1]);
    *(float2*)(dB + d0 + 8 + 2*tig) = make_float2(o1[2], o1[3]);
  }
}

// ---------------- stage 5: combine hashes, merge heads (float4) ----------------
__global__ void combine_kernel(){
  int idx = blockIdx.x*blockDim.x + threadIdx.x;
  if (idx >= BHDIM*T*8) return;
  int dq  = idx & 7;
  int pos = (idx >> 3) % 640;
  int bh  = idx / (640*8);
  float l[NHASH];
  #pragma unroll
  for (int h=0;h<NHASH;h++) l[h] = g_logit[(bh*NHASH+h)*T + pos];
  float m = l[0];
  #pragma unroll
  for (int h=1;h<NHASH;h++) m = fmaxf(m, l[h]);
  float s = 0.f;
  float e[NHASH];
  #pragma unroll
  for (int h=0;h<NHASH;h++){ e[h] = __expf(l[h]-m); s += e[h]; }
  float inv = 1.f/s;
  float4 acc = make_float4(0.f,0.f,0.f,0.f);
  #pragma unroll
  for (int h=0;h<NHASH;h++){
    float w = e[h]*inv;
    float4 v = *(const float4*)(g_ohash + ((size_t)(bh*NHASH+h)*T + pos)*32 + dq*4);
    acc.x += w*v.x; acc.y += w*v.y; acc.z += w*v.z; acc.w += w*v.w;
  }
  int b = bh>>3, head = bh&7;
  *(float4*)(g_omerged + ((size_t)b*640 + pos)*256 + head*32 + dq*4) = acc;
}

// ---------------- stage 6: output GEMM + bias, 2xTF32 (A split, B rna plane) ----------------
__global__ __launch_bounds__(256) void gemm_out_tc(const float* __restrict__ bias,
                                                   float* __restrict__ out){
  __shared__ float s_a[128*36];
  __shared__ float s_bh[64*36];

  int tid = threadIdx.x;
  int m0 = blockIdx.y*128, n0 = blockIdx.x*64;
  int warp = tid>>5, lane = tid&31;
  int g = lane>>2, tig = lane&3;
  int rA = warp*16 + g, rB = rA + 8;

  float acc[8][4];
  #pragma unroll
  for (int nt=0;nt<8;nt++)
    #pragma unroll
    for (int u=0;u<4;u++) acc[nt][u]=0.f;

  for (int kc=0;kc<EMBD;kc+=32){
    __syncthreads();
    {
      int row = tid>>1, half = (tid&1)*16;
      const float* asrc = g_omerged + (size_t)(m0+row)*EMBD + kc + half;
      #pragma unroll
      for (int u=0;u<16;u+=4)
        *(float4*)&s_a[row*36 + half + u] = *(const float4*)(asrc+u);
    }
    {
      int n = tid>>2, kq = (tid&3)*8;
      size_t bo = (size_t)(n0+n)*EMBD + kc + kq;
      *(float4*)&s_bh[n*36+kq]   = *(const float4*)&g_woT_hi[bo];
      *(float4*)&s_bh[n*36+kq+4] = *(const float4*)&g_woT_hi[bo+4];
    }
    __syncthreads();

    #pragma unroll
    for (int kk=0;kk<32;kk+=8){
      unsigned ah[4], al[4];
      tf32_split(s_a[rA*36+kk+tig],   ah[0], al[0]);
      tf32_split(s_a[rB*36+kk+tig],   ah[1], al[1]);
      tf32_split(s_a[rA*36+kk+tig+4], ah[2], al[2]);
      tf32_split(s_a[rB*36+kk+tig+4], ah[3], al[3]);
      #pragma unroll
      for (int nt=0;nt<8;nt++){
        int nr = nt*8 + g;
        unsigned bhv[2] = { fu(s_bh[nr*36+kk+tig]), fu(s_bh[nr*36+kk+tig+4]) };
        mma_tf32(acc[nt], ah, bhv);
        mma_tf32(acc[nt], al, bhv);
      }
    }
  }
  int rowA = m0 + rA, rowB = m0 + rB;
  #pragma unroll
  for (int nt=0;nt<8;nt++){
    int col = n0 + nt*8 + 2*tig;
    float b0 = __ldg(bias+col), b1 = __ldg(bias+col+1);
    *(float2*)&out[(size_t)rowA*EMBD + col] = make_float2(acc[nt][0]+b0, acc[nt][1]+b1);
    *(float2*)&out[(size_t)rowB*EMBD + col] = make_float2(acc[nt][2]+b0, acc[nt][3]+b1);
  }
}

// ---------------- launch ----------------
extern "C" void kernel_launch(void* const* d_in, const int* in_sizes, int n_in,
                              void* d_out, int out_size){
  const float* x     = (const float*)d_in[0];
  const float* w_qk  = (const float*)d_in[1];
  const float* w_v   = (const float*)d_in[2];
  const float* w_out = (const float*)d_in[3];
  const float* b_out = (const float*)d_in[4];
  const float* rot   = (const float*)d_in[5];
  float* out = (float*)d_out;

  wsplit_kernel<<<dim3(8,8,3), dim3(32,8)>>>(w_qk, w_v, w_out);
  frontend_kernel<<<BATCH*128, 256>>>(x);
  cudaFuncSetAttribute(gemm_qkv_tc, cudaFuncAttributeMaxDynamicSharedMemorySize, SMEM_QKV);
  gemm_qkv_tc<<<dim3(4,80), 256, SMEM_QKV>>>();
  bucket_kernel<<<dim3(BHDIM, T/128), 256>>>(rot);
  sort_kernel<<<BHDIM*NHASH, 320>>>();
  cudaFuncSetAttribute(attn_kernel, cudaFuncAttributeMaxDynamicSharedMemorySize, SMEM_ATTN);
  attn_kernel<<<BHDIM*NCHUNK, 256, SMEM_ATTN>>>();
  combine_kernel<<<(BHDIM*T*8+255)/256, 256>>>();
  gemm_out_tc<<<dim3(4,80), 256>>>(b_out, out);
}

// round 16
// speedup vs baseline: 1.2557x; 1.0242x over previous
#include <cuda_runtime.h>
#include <math.h>

#define BATCH   16
#define T       640
#define EMBD    256
#define HEADS   8
#define DHDIM   32
#define BHDIM   128      // BATCH*HEADS
#define NHASH   8
#define NCHUNK  80
#define NROWS   10240    // BATCH*T

// ---------------- scratch (device globals; no allocation allowed) ----------------
__device__ float g_tokens[NROWS*EMBD];
__device__ float g_qk[BHDIM*T*DHDIM];
__device__ float g_v [BHDIM*T*DHDIM];
__device__ int   g_bucket[BHDIM*NHASH*T];
__device__ int   g_sorted[BHDIM*NHASH*T];
__device__ float g_ohash[(size_t)BHDIM*NHASH*T*DHDIM];
__device__ float g_logit[BHDIM*NHASH*T];
__device__ float g_omerged[NROWS*EMBD];
// pre-transposed + pre-split weights: [n][k] layout, hi/lo planes
__device__ float g_wqkT_hi[EMBD*EMBD], g_wqkT_lo[EMBD*EMBD];
__device__ float g_wvT_hi [EMBD*EMBD], g_wvT_lo [EMBD*EMBD];
__device__ float g_woT_hi [EMBD*EMBD], g_woT_lo [EMBD*EMBD];

// ---------------- tf32 mma.sync helpers ----------------
__device__ __forceinline__ void mma_tf32(float* d, const unsigned* a, const unsigned* b){
  asm volatile(
    "mma.sync.aligned.m16n8k8.row.col.f32.tf32.tf32.f32 "
    "{%0,%1,%2,%3}, {%4,%5,%6,%7}, {%8,%9}, {%0,%1,%2,%3};"
    : "+f"(d[0]), "+f"(d[1]), "+f"(d[2]), "+f"(d[3])
    : "r"(a[0]), "r"(a[1]), "r"(a[2]), "r"(a[3]), "r"(b[0]), "r"(b[1]));
}
// cheap split: hi = x with low 13 mantissa bits zeroed (exact tf32 value), lo = x - hi
__device__ __forceinline__ void tf32_split(float x, unsigned &hi, unsigned &lo){
  unsigned hb = __float_as_uint(x) & 0xFFFFE000u;
  hi = hb;
  lo = __float_as_uint(x - __uint_as_float(hb));
}
// round-to-nearest tf32 (zero-mean rounding; result has low 13 bits zero, so
// feeding the stored float straight to mma.tf32 is a no-op truncation)
__device__ __forceinline__ unsigned tf32_rna(float x){
  unsigned u; asm("cvt.rna.tf32.f32 %0, %1;" : "=r"(u) : "f"(x)); return u;
}
__device__ __forceinline__ float tf32_rnaf(float x){
  return __uint_as_float(tf32_rna(x));
}
__device__ __forceinline__ unsigned fu(float x){ return __float_as_uint(x); }

// ---------------- stage 0: weight transpose + split ----------------
// z==0,1 (wqk, wv): truncation hi/lo planes (exact 3xTF32 path)
// z==2   (wo):      hi = rna-rounded single plane (2xTF32 path), lo unused
__global__ void wsplit_kernel(const float* __restrict__ wqk,
                              const float* __restrict__ wv,
                              const float* __restrict__ wo){
  __shared__ float tile[32][33];
  int z = blockIdx.z;
  const float* src = (z==0) ? wqk : (z==1) ? wv : wo;
  float* dh = (z==0) ? g_wqkT_hi : (z==1) ? g_wvT_hi : g_woT_hi;
  float* dl = (z==0) ? g_wqkT_lo : (z==1) ? g_wvT_lo : g_woT_lo;
  int n0 = blockIdx.x*32, k0 = blockIdx.y*32;
  #pragma unroll
  for (int r=0;r<4;r++){
    int k = threadIdx.y + r*8;
    tile[k][threadIdx.x] = src[(k0+k)*EMBD + n0 + threadIdx.x];
  }
  __syncthreads();
  #pragma unroll
  for (int r=0;r<4;r++){
    int n = threadIdx.y + r*8;
    float v = tile[threadIdx.x][n];
    int oi = (n0+n)*EMBD + k0 + threadIdx.x;
    if (z == 2){
      dh[oi] = tf32_rnaf(v);
      dl[oi] = 0.f;
    } else {
      float hv = __uint_as_float(__float_as_uint(v) & 0xFFFFE000u);
      dh[oi] = hv;
      dl[oi] = v - hv;
    }
  }
}

// ---------------- stage 1: maxpool + Haar DWT -> tokens (smem tiled) ----------------
__global__ __launch_bounds__(256) void frontend_kernel(const float* __restrict__ x){
  __shared__ float s_x[32][33];
  int plane = blockIdx.x;            // b*128 + ch
  int b = plane >> 7, ch = plane & 127;
  const float* xp = x + (size_t)plane*1024;
  int t = threadIdx.x;

  {
    float4 v = *(const float4*)(xp + t*4);
    int r = t >> 3, c4 = (t & 7)*4;
    s_x[r][c4]=v.x; s_x[r][c4+1]=v.y; s_x[r][c4+2]=v.z; s_x[r][c4+3]=v.w;
  }
  __syncthreads();

  int i = t >> 4, j = t & 15;
  float m = -INFINITY;
  int r0 = 2*i-1, c0 = 2*j-1;
  #pragma unroll
  for (int dr=0;dr<3;dr++){
    int r = r0+dr; if (r<0 || r>31) continue;
    #pragma unroll
    for (int dc=0;dc<3;dc++){
      int cc = c0+dc; if (cc<0 || cc>31) continue;
      m = fmaxf(m, s_x[r][cc]);
    }
  }
  float a  = s_x[2*i][2*j];
  float bb = s_x[2*i][2*j+1];
  float c  = s_x[2*i+1][2*j];
  float d  = s_x[2*i+1][2*j+1];
  float ll = (a+bb+c+d)*0.5f;
  float lh = (a-bb+c-d)*0.5f;
  float hl = (a+bb-c-d)*0.5f;
  float hh = (a-bb-c+d)*0.5f;

  size_t rowbase = (size_t)b*640;
  g_tokens[(rowbase + ch      )*256 + t] = m;
  g_tokens[(rowbase + 128 + ch)*256 + t] = ll;
  g_tokens[(rowbase + 256 + ch)*256 + t] = lh;
  g_tokens[(rowbase + 384 + ch)*256 + t] = hl;
  g_tokens[(rowbase + 512 + ch)*256 + t] = hh;
}

// ---------------- stage 2: fused qk/v GEMM, 3xTF32 tensor cores ----------------
#define SMEM_QKV ((128*36 + 4*64*36)*4)

__global__ __launch_bounds__(256) void gemm_qkv_tc(){
  extern __shared__ float sm[];
  float* s_a   = sm;                 // [128][36]
  float* s_b1h = s_a   + 128*36;     // [64][36]
  float* s_b1l = s_b1h + 64*36;
  float* s_b2h = s_b1l + 64*36;
  float* s_b2l = s_b2h + 64*36;

  int tid = threadIdx.x;
  int m0 = blockIdx.y*128, n0 = blockIdx.x*64;
  int warp = tid>>5, lane = tid&31;
  int g = lane>>2, tig = lane&3;
  int rA = warp*16 + g, rB = rA + 8;

  float acc1[8][4], acc2[8][4];
  #pragma unroll
  for (int nt=0;nt<8;nt++)
    #pragma unroll
    for (int u=0;u<4;u++){ acc1[nt][u]=0.f; acc2[nt][u]=0.f; }

  for (int kc=0;kc<EMBD;kc+=32){
    __syncthreads();
    {
      int row = tid>>1, half = (tid&1)*16;
      const float* asrc = g_tokens + (size_t)(m0+row)*EMBD + kc + half;
      #pragma unroll
      for (int u=0;u<16;u+=4)
        *(float4*)&s_a[row*36 + half + u] = *(const float4*)(asrc+u);
    }
    {
      int n = tid>>2, kq = (tid&3)*8;
      size_t bo = (size_t)(n0+n)*EMBD + kc + kq;
      *(float4*)&s_b1h[n*36+kq]   = *(const float4*)&g_wqkT_hi[bo];
      *(float4*)&s_b1h[n*36+kq+4] = *(const float4*)&g_wqkT_hi[bo+4];
      *(float4*)&s_b1l[n*36+kq]   = *(const float4*)&g_wqkT_lo[bo];
      *(float4*)&s_b1l[n*36+kq+4] = *(const float4*)&g_wqkT_lo[bo+4];
      *(float4*)&s_b2h[n*36+kq]   = *(const float4*)&g_wvT_hi[bo];
      *(float4*)&s_b2h[n*36+kq+4] = *(const float4*)&g_wvT_hi[bo+4];
      *(float4*)&s_b2l[n*36+kq]   = *(const float4*)&g_wvT_lo[bo];
      *(float4*)&s_b2l[n*36+kq+4] = *(const float4*)&g_wvT_lo[bo+4];
    }
    __syncthreads();

    #pragma unroll
    for (int kk=0;kk<32;kk+=8){
      unsigned ah[4], al[4];
      tf32_split(s_a[rA*36+kk+tig],   ah[0], al[0]);
      tf32_split(s_a[rB*36+kk+tig],   ah[1], al[1]);
      tf32_split(s_a[rA*36+kk+tig+4], ah[2], al[2]);
      tf32_split(s_a[rB*36+kk+tig+4], ah[3], al[3]);
      #pragma unroll
      for (int nt=0;nt<8;nt++){
        int nr = nt*8 + g;
        unsigned b1h[2] = { fu(s_b1h[nr*36+kk+tig]), fu(s_b1h[nr*36+kk+tig+4]) };
        unsigned b1l[2] = { fu(s_b1l[nr*36+kk+tig]), fu(s_b1l[nr*36+kk+tig+4]) };
        mma_tf32(acc1[nt], ah, b1h);
        mma_tf32(acc1[nt], al, b1h);
        mma_tf32(acc1[nt], ah, b1l);
        unsigned b2h[2] = { fu(s_b2h[nr*36+kk+tig]), fu(s_b2h[nr*36+kk+tig+4]) };
        unsigned b2l[2] = { fu(s_b2l[nr*36+kk+tig]), fu(s_b2l[nr*36+kk+tig+4]) };
        mma_tf32(acc2[nt], ah, b2h);
        mma_tf32(acc2[nt], al, b2h);
        mma_tf32(acc2[nt], ah, b2l);
      }
    }
  }
  int rowA = m0 + rA, rowB = m0 + rB;
  int bA = rowA/640, tokA = rowA - bA*640;
  int bB = rowB/640, tokB = rowB - bB*640;
  #pragma unroll
  for (int nt=0;nt<8;nt++){
    int col = n0 + nt*8 + 2*tig;
    int head = col>>5, dh = col&31;
    size_t oA = ((size_t)(bA*8+head)*640 + tokA)*32 + dh;
    size_t oB = ((size_t)(bB*8+head)*640 + tokB)*32 + dh;
    *(float2*)&g_qk[oA] = make_float2(acc1[nt][0], acc1[nt][1]);
    *(float2*)&g_v [oA] = make_float2(acc2[nt][0], acc2[nt][1]);
    *(float2*)&g_qk[oB] = make_float2(acc1[nt][2], acc1[nt][3]);
    *(float2*)&g_v [oB] = make_float2(acc2[nt][2], acc2[nt][3]);
  }
}

// ---------------- stage 3a: LSH bucket ids — warp-per-hash, 4 pos/thread ----------------
__global__ __launch_bounds__(256) void bucket_kernel(const float* __restrict__ rot){
  __shared__ float s_rot[1280];        // [f=32][h=8][i=5]
  __shared__ float s_q[128][33];
  int bh = blockIdx.x, pos0 = blockIdx.y*128;
  int tid = threadIdx.x;

  for (int i=tid;i<1280;i+=256) s_rot[i]=rot[i];
  {
    int row = tid>>1, fh = (tid&1)*16;
    const float* src = g_qk + ((size_t)bh*640 + pos0 + row)*32 + fh;
    #pragma unroll
    for (int u=0;u<16;u+=4){
      float4 v = *(const float4*)(src+u);
      s_q[row][fh+u]=v.x; s_q[row][fh+u+1]=v.y; s_q[row][fh+u+2]=v.z; s_q[row][fh+u+3]=v.w;
    }
  }
  __syncthreads();

  int h = tid>>5, l = tid&31;
  float r5[4][5];
  #pragma unroll
  for (int k=0;k<4;k++)
    #pragma unroll
    for (int i=0;i<5;i++) r5[k][i]=0.f;

  #pragma unroll 4
  for (int f=0;f<32;f++){
    const float* rp = s_rot + f*40 + h*5;   // warp-uniform -> broadcast
    float w0=rp[0], w1=rp[1], w2=rp[2], w3=rp[3], w4=rp[4];
    #pragma unroll
    for (int k=0;k<4;k++){
      float qf = s_q[l + 32*k][f];
      r5[k][0] += qf*w0; r5[k][1] += qf*w1; r5[k][2] += qf*w2;
      r5[k][3] += qf*w3; r5[k][4] += qf*w4;
    }
  }
  #pragma unroll
  for (int k=0;k<4;k++){
    float best = r5[k][0]; int bi = 0;
    #pragma unroll
    for (int i=1;i<5;i++) if (r5[k][i] > best){ best=r5[k][i]; bi=i; }
    #pragma unroll
    for (int i=0;i<5;i++){ float v = -r5[k][i]; if (v > best){ best=v; bi=5+i; } }
    g_bucket[(size_t)bh*NHASH*T + h*640 + pos0 + l + 32*k] = bi;
  }
}

// ---------------- stage 3b: stable counting sort per (bh, hash) — smem staged ----------------
__global__ __launch_bounds__(320) void sort_kernel(){
  __shared__ int s_bk[640];
  __shared__ int cnt[10], off[10];
  int bhh = blockIdx.x;
  const int* bk = g_bucket + bhh*640;
  for (int i=threadIdx.x;i<640;i+=320) s_bk[i]=bk[i];
  __syncthreads();

  int w = threadIdx.x>>5, lane = threadIdx.x&31;
  int count = 0;
  for (int base=0;base<640;base+=32){
    int bb = s_bk[base+lane];
    unsigned mask = __ballot_sync(0xffffffffu, bb==w);
    count += __popc(mask);
  }
  if (lane==0) cnt[w] = count;
  __syncthreads();
  if (threadIdx.x==0){
    int run=0;
    for (int b=0;b<10;b++){ off[b]=run; run+=cnt[b]; }
  }
  __syncthreads();
  int base_off = off[w]; int run = 0;
  int* out = g_sorted + bhh*640;
  for (int base=0;base<640;base+=32){
    int bb = s_bk[base+lane];
    unsigned mask = __ballot_sync(0xffffffffu, bb==w);
    if (bb==w){
      int slot = base_off + run + __popc(mask & ((1u<<lane)-1u));
      out[slot] = base+lane;
    }
    run += __popc(mask);
  }
}

// ---------------- stage 4: chunked attention, 1xTF32, rna hoisted to loaders ----------------
#define Q_PAD 36
#define K_PAD 36
#define V_PAD 40
#define P_PAD 132
#define SMEM_ATTN ((64*P_PAD + 128*V_PAD + 2*128)*4 + (64+128)*4)

__global__ __launch_bounds__(256) void attn_kernel(){
  extern __shared__ char smem_raw[];
  float* s_p    = (float*)smem_raw;          // [64][132]
  float* s_q    = s_p;                       // [64][36]  alias
  float* s_k    = s_p + 64*Q_PAD;            // [128][36] alias
  float* s_v    = s_p + 64*P_PAD;            // [128][40]
  float* s_redm = s_v + 128*V_PAD;           // [2][64]
  float* s_reds = s_redm + 128;              // [2][64]
  int*   s_qt   = (int*)(s_reds + 128);      // [64]
  int*   s_kt   = s_qt + 64;                 // [128]

  int tid = threadIdx.x;
  int blk = blockIdx.x;
  int bh = blk / NCHUNK, c = blk % NCHUNK;
  int h  = c / 10;
  int pc = (c + NCHUNK - 1) % NCHUNK;
  int ph = pc / 10;
  const int* sortedbh = g_sorted + bh*NHASH*T;

  if (tid < 64)
    s_qt[tid] = sortedbh[h*640 + (c%10)*64 + tid];
  else if (tid < 192){
    int j = tid - 64;
    s_kt[j] = (j < 64) ? sortedbh[h*640 + (c%10)*64 + j]
                       : sortedbh[ph*640 + (pc%10)*64 + (j-64)];
  }
  __syncthreads();

  // Q loader: pre-rna (dots consumes rna(q))
  {
    int i = tid >> 2, f0 = (tid & 3) * 8;
    const float* src = g_qk + ((size_t)bh*640 + s_qt[i])*32 + f0;
    float4 a = *(const float4*)src;
    float4 b = *(const float4*)(src+4);
    s_q[i*Q_PAD+f0  ]=tf32_rnaf(a.x); s_q[i*Q_PAD+f0+1]=tf32_rnaf(a.y);
    s_q[i*Q_PAD+f0+2]=tf32_rnaf(a.z); s_q[i*Q_PAD+f0+3]=tf32_rnaf(a.w);
    s_q[i*Q_PAD+f0+4]=tf32_rnaf(b.x); s_q[i*Q_PAD+f0+5]=tf32_rnaf(b.y);
    s_q[i*Q_PAD+f0+6]=tf32_rnaf(b.z); s_q[i*Q_PAD+f0+7]=tf32_rnaf(b.w);
  }
  // K loader: normalize (exact fp32) then pre-rna
  {
    int j = tid >> 1, fh = (tid & 1) * 16;
    const float* src = g_qk + ((size_t)bh*640 + s_kt[j])*32 + fh;
    float buf[16]; float ss = 0.f;
    #pragma unroll
    for (int u=0;u<16;u+=4){
      float4 a = *(const float4*)(src+u);
      buf[u]=a.x; buf[u+1]=a.y; buf[u+2]=a.z; buf[u+3]=a.w;
      ss += a.x*a.x + a.y*a.y + a.z*a.z + a.w*a.w;
    }
    ss += __shfl_xor_sync(0xffffffffu, ss, 1);
    float inv = 1.f / fmaxf(sqrtf(ss), 1e-6f);
    #pragma unroll
    for (int u=0;u<16;u++)
      s_k[j*K_PAD + fh + u] = tf32_rnaf(buf[u]*inv);
  }
  // V loader: pre-rna
  {
    int j = tid >> 1, fh = (tid & 1) * 16;
    const float* src = g_v + ((size_t)bh*640 + s_kt[j])*32 + fh;
    #pragma unroll
    for (int u=0;u<16;u+=4){
      float4 a = *(const float4*)(src+u);
      s_v[j*V_PAD+fh+u  ]=tf32_rnaf(a.x); s_v[j*V_PAD+fh+u+1]=tf32_rnaf(a.y);
      s_v[j*V_PAD+fh+u+2]=tf32_rnaf(a.z); s_v[j*V_PAD+fh+u+3]=tf32_rnaf(a.w);
    }
  }
  __syncthreads();

  int warp = tid >> 5, lane = tid & 31;
  int wm = warp & 3, wn = warp >> 2;
  int g = lane >> 2, tig = lane & 3;
  int m0 = wm * 16;
  int rA = m0 + g, rB = m0 + g + 8;

  // ---- dots: S(16x64 per warp) = Q x K^T, 1xTF32, raw LDS (pre-rounded) ----
  float acc[8][4];
  #pragma unroll
  for (int nt=0;nt<8;nt++)
    #pragma unroll
    for (int u=0;u<4;u++) acc[nt][u] = 0.f;

  #pragma unroll
  for (int k0=0;k0<32;k0+=8){
    unsigned aq[4];
    aq[0] = fu(s_q[rA*Q_PAD + k0 + tig]);
    aq[1] = fu(s_q[rB*Q_PAD + k0 + tig]);
    aq[2] = fu(s_q[rA*Q_PAD + k0 + tig + 4]);
    aq[3] = fu(s_q[rB*Q_PAD + k0 + tig + 4]);
    #pragma unroll
    for (int nt=0;nt<8;nt++){
      int n0 = wn*64 + nt*8;
      unsigned bhh[2];
      bhh[0] = fu(s_k[(n0+g)*K_PAD + k0 + tig]);
      bhh[1] = fu(s_k[(n0+g)*K_PAD + k0 + tig + 4]);
      mma_tf32(acc[nt], aq, bhh);
    }
  }

  int qtA = s_qt[rA], qtB = s_qt[rB];
  #pragma unroll
  for (int nt=0;nt<8;nt++){
    int n0 = wn*64 + nt*8;
    int kt0 = s_kt[n0 + 2*tig], kt1 = s_kt[n0 + 2*tig + 1];
    acc[nt][0] = (kt0==qtA) ? -50000.f : acc[nt][0]*0.17677669529663687f;
    acc[nt][1] = (kt1==qtA) ? -50000.f : acc[nt][1]*0.17677669529663687f;
    acc[nt][2] = (kt0==qtB) ? -50000.f : acc[nt][2]*0.17677669529663687f;
    acc[nt][3] = (kt1==qtB) ? -50000.f : acc[nt][3]*0.17677669529663687f;
  }

  float mA=-INFINITY, mB=-INFINITY;
  #pragma unroll
  for (int nt=0;nt<8;nt++){
    mA = fmaxf(mA, fmaxf(acc[nt][0], acc[nt][1]));
    mB = fmaxf(mB, fmaxf(acc[nt][2], acc[nt][3]));
  }
  #pragma unroll
  for (int o=1;o<=2;o<<=1){
    mA = fmaxf(mA, __shfl_xor_sync(0xffffffffu, mA, o, 4));
    mB = fmaxf(mB, __shfl_xor_sync(0xffffffffu, mB, o, 4));
  }
  float sA=0.f, sB=0.f;
  #pragma unroll
  for (int nt=0;nt<8;nt++){
    acc[nt][0] = __expf(acc[nt][0]-mA);
    acc[nt][1] = __expf(acc[nt][1]-mA);
    acc[nt][2] = __expf(acc[nt][2]-mB);
    acc[nt][3] = __expf(acc[nt][3]-mB);
    sA += acc[nt][0] + acc[nt][1];
    sB += acc[nt][2] + acc[nt][3];
  }
  #pragma unroll
  for (int o=1;o<=2;o<<=1){
    sA += __shfl_xor_sync(0xffffffffu, sA, o, 4);
    sB += __shfl_xor_sync(0xffffffffu, sB, o, 4);
  }
  if (tig == 0){
    s_redm[wn*64 + rA] = mA;  s_reds[wn*64 + rA] = sA;
    s_redm[wn*64 + rB] = mB;  s_reds[wn*64 + rB] = sB;
  }
  __syncthreads();

  float lseA, lseB;
  {
    float m0A = s_redm[rA], m1A = s_redm[64+rA];
    float mm = fmaxf(m0A, m1A);
    float ss = s_reds[rA]*__expf(m0A-mm) + s_reds[64+rA]*__expf(m1A-mm);
    lseA = mm + __logf(ss);
    float m0B = s_redm[rB], m1B = s_redm[64+rB];
    mm = fmaxf(m0B, m1B);
    ss = s_reds[rB]*__expf(m0B-mm) + s_reds[64+rB]*__expf(m1B-mm);
    lseB = mm + __logf(ss);
  }
  if (wn == 0 && tig == 0){
    g_logit[(bh*NHASH+h)*T + qtA] = lseA;
    g_logit[(bh*NHASH+h)*T + qtB] = lseB;
  }

  // probs store: pre-rna (PV consumes rna(p))
  float scA = __expf(mA - lseA);
  float scB = __expf(mB - lseB);
  #pragma unroll
  for (int nt=0;nt<8;nt++){
    int n0 = wn*64 + nt*8;
    *(float2*)&s_p[rA*P_PAD + n0 + 2*tig] =
      make_float2(tf32_rnaf(acc[nt][0]*scA), tf32_rnaf(acc[nt][1]*scA));
    *(float2*)&s_p[rB*P_PAD + n0 + 2*tig] =
      make_float2(tf32_rnaf(acc[nt][2]*scB), tf32_rnaf(acc[nt][3]*scB));
  }
  __syncthreads();

  // ---- PV: 1xTF32, raw LDS (everything pre-rounded) ----
  float o0[4] = {0.f,0.f,0.f,0.f};
  float o1[4] = {0.f,0.f,0.f,0.f};
  int d0 = wn*16;
  #pragma unroll 2
  for (int k0=0;k0<128;k0+=8){
    unsigned ap[4];
    ap[0] = fu(s_p[rA*P_PAD + k0 + tig]);
    ap[1] = fu(s_p[rB*P_PAD + k0 + tig]);
    ap[2] = fu(s_p[rA*P_PAD + k0 + tig + 4]);
    ap[3] = fu(s_p[rB*P_PAD + k0 + tig + 4]);
    unsigned b0h[2], b1h[2];
    b0h[0] = fu(s_v[(k0+tig)*V_PAD   + d0 + g]);
    b0h[1] = fu(s_v[(k0+tig+4)*V_PAD + d0 + g]);
    b1h[0] = fu(s_v[(k0+tig)*V_PAD   + d0 + 8 + g]);
    b1h[1] = fu(s_v[(k0+tig+4)*V_PAD + d0 + 8 + g]);
    mma_tf32(o0, ap, b0h);
    mma_tf32(o1, ap, b1h);
  }
  {
    size_t base = (size_t)(bh*NHASH+h)*T;
    float* dA = g_ohash + (base + qtA)*32;
    float* dB = g_ohash + (base + qtB)*32;
    *(float2*)(dA + d0 + 2*tig)     = make_float2(o0[0], o0[1]);
    *(float2*)(dB + d0 + 2*tig)     = make_float2(o0[2], o0[3]);
    *(float2*)(dA + d0 + 8 + 2*tig) = make_float2(o1[0], o1[1]);
    *(float2*)(dB + d0 + 8 + 2*tig) = make_float2(o1[2], o1[3]);
  }
}

// ---------------- stage 5: combine hashes, merge heads (float4) ----------------
__global__ void combine_kernel(){
  int idx = blockIdx.x*blockDim.x + threadIdx.x;
  if (idx >= BHDIM*T*8) return;
  int dq  = idx & 7;
  int pos = (idx >> 3) % 640;
  int bh  = idx / (640*8);
  float l[NHASH];
  #pragma unroll
  for (int h=0;h<NHASH;h++) l[h] = g_logit[(bh*NHASH+h)*T + pos];
  float m = l[0];
  #pragma unroll
  for (int h=1;h<NHASH;h++) m = fmaxf(m, l[h]);
  float s = 0.f;
  float e[NHASH];
  #pragma unroll
  for (int h=0;h<NHASH;h++){ e[h] = __expf(l[h]-m); s += e[h]; }
  float inv = 1.f/s;
  float4 acc = make_float4(0.f,0.f,0.f,0.f);
  #pragma unroll
  for (int h=0;h<NHASH;h++){
    float w = e[h]*inv;
    float4 v = *(const float4*)(g_ohash + ((size_t)(bh*NHASH+h)*T + pos)*32 + dq*4);
    acc.x += w*v.x; acc.y += w*v.y; acc.z += w*v.z; acc.w += w*v.w;
  }
  int b = bh>>3, head = bh&7;
  *(float4*)(g_omerged + ((size_t)b*640 + pos)*256 + head*32 + dq*4) = acc;
}

// ---------------- stage 6: output GEMM + bias, 2xTF32 (A split, B rna plane) ----------------
__global__ __launch_bounds__(256) void gemm_out_tc(const float* __restrict__ bias,
                                                   float* __restrict__ out){
  __shared__ float s_a[128*36];
  __shared__ float s_bh[64*36];

  int tid = threadIdx.x;
  int m0 = blockIdx.y*128, n0 = blockIdx.x*64;
  int warp = tid>>5, lane = tid&31;
  int g = lane>>2, tig = lane&3;
  int rA = warp*16 + g, rB = rA + 8;

  float acc[8][4];
  #pragma unroll
  for (int nt=0;nt<8;nt++)
    #pragma unroll
    for (int u=0;u<4;u++) acc[nt][u]=0.f;

  for (int kc=0;kc<EMBD;kc+=32){
    __syncthreads();
    {
      int row = tid>>1, half = (tid&1)*16;
      const float* asrc = g_omerged + (size_t)(m0+row)*EMBD + kc + half;
      #pragma unroll
      for (int u=0;u<16;u+=4)
        *(float4*)&s_a[row*36 + half + u] = *(const float4*)(asrc+u);
    }
    {
      int n = tid>>2, kq = (tid&3)*8;
      size_t bo = (size_t)(n0+n)*EMBD + kc + kq;
      *(float4*)&s_bh[n*36+kq]   = *(const float4*)&g_woT_hi[bo];
      *(float4*)&s_bh[n*36+kq+4] = *(const float4*)&g_woT_hi[bo+4];
    }
    __syncthreads();

    #pragma unroll
    for (int kk=0;kk<32;kk+=8){
      unsigned ah[4], al[4];
      tf32_split(s_a[rA*36+kk+tig],   ah[0], al[0]);
      tf32_split(s_a[rB*36+kk+tig],   ah[1], al[1]);
      tf32_split(s_a[rA*36+kk+tig+4], ah[2], al[2]);
      tf32_split(s_a[rB*36+kk+tig+4], ah[3], al[3]);
      #pragma unroll
      for (int nt=0;nt<8;nt++){
        int nr = nt*8 + g;
        unsigned bhv[2] = { fu(s_bh[nr*36+kk+tig]), fu(s_bh[nr*36+kk+tig+4]) };
        mma_tf32(acc[nt], ah, bhv);
        mma_tf32(acc[nt], al, bhv);
      }
    }
  }
  int rowA = m0 + rA, rowB = m0 + rB;
  #pragma unroll
  for (int nt=0;nt<8;nt++){
    int col = n0 + nt*8 + 2*tig;
    float b0 = __ldg(bias+col), b1 = __ldg(bias+col+1);
    *(float2*)&out[(size_t)rowA*EMBD + col] = make_float2(acc[nt][0]+b0, acc[nt][1]+b1);
    *(float2*)&out[(size_t)rowB*EMBD + col] = make_float2(acc[nt][2]+b0, acc[nt][3]+b1);
  }
}

// ---------------- launch ----------------
extern "C" void kernel_launch(void* const* d_in, const int* in_sizes, int n_in,
                              void* d_out, int out_size){
  const float* x     = (const float*)d_in[0];
  const float* w_qk  = (const float*)d_in[1];
  const float* w_v   = (const float*)d_in[2];
  const float* w_out = (const float*)d_in[3];
  const float* b_out = (const float*)d_in[4];
  const float* rot   = (const float*)d_in[5];
  float* out = (float*)d_out;

  wsplit_kernel<<<dim3(8,8,3), dim3(32,8)>>>(w_qk, w_v, w_out);
  frontend_kernel<<<BATCH*128, 256>>>(x);
  cudaFuncSetAttribute(gemm_qkv_tc, cudaFuncAttributeMaxDynamicSharedMemorySize, SMEM_QKV);
  gemm_qkv_tc<<<dim3(4,80), 256, SMEM_QKV>>>();
  bucket_kernel<<<dim3(BHDIM, T/128), 256>>>(rot);
  sort_kernel<<<BHDIM*NHASH, 320>>>();
  cudaFuncSetAttribute(attn_kernel, cudaFuncAttributeMaxDynamicSharedMemorySize, SMEM_ATTN);
  attn_kernel<<<BHDIM*NCHUNK, 256, SMEM_ATTN>>>();
  combine_kernel<<<(BHDIM*T*8+255)/256, 256>>>();
  gemm_out_tc<<<dim3(4,80), 256>>>(b_out, out);
}

// round 17
// speedup vs baseline: 1.2900x; 1.0273x over previous
#include <cuda_runtime.h>
#include <math.h>

#define BATCH   16
#define T       640
#define EMBD    256
#define HEADS   8
#define DHDIM   32
#define BHDIM   128      // BATCH*HEADS
#define NHASH   8
#define NCHUNK  80
#define NROWS   10240    // BATCH*T

// ---------------- scratch (device globals; no allocation allowed) ----------------
__device__ float g_tokens[NROWS*EMBD];
__device__ float g_qk[BHDIM*T*DHDIM];
__device__ float g_v [BHDIM*T*DHDIM];
__device__ int   g_bucket[BHDIM*NHASH*T];
__device__ int   g_sorted[BHDIM*NHASH*T];
__device__ float g_oacc[NROWS*EMBD];     // merged-head weighted accumulator
__device__ float g_wsum[BHDIM*T];        // per (bh,pos) sum of exp(lse)
// pre-transposed + pre-split weights: [n][k] layout, hi/lo planes
__device__ float g_wqkT_hi[EMBD*EMBD], g_wqkT_lo[EMBD*EMBD];
__device__ float g_wvT_hi [EMBD*EMBD], g_wvT_lo [EMBD*EMBD];
__device__ float g_woT_hi [EMBD*EMBD], g_woT_lo [EMBD*EMBD];

// ---------------- tf32 mma.sync helpers ----------------
__device__ __forceinline__ void mma_tf32(float* d, const unsigned* a, const unsigned* b){
  asm volatile(
    "mma.sync.aligned.m16n8k8.row.col.f32.tf32.tf32.f32 "
    "{%0,%1,%2,%3}, {%4,%5,%6,%7}, {%8,%9}, {%0,%1,%2,%3};"
    : "+f"(d[0]), "+f"(d[1]), "+f"(d[2]), "+f"(d[3])
    : "r"(a[0]), "r"(a[1]), "r"(a[2]), "r"(a[3]), "r"(b[0]), "r"(b[1]));
}
// cheap split: hi = x with low 13 mantissa bits zeroed (exact tf32 value), lo = x - hi
__device__ __forceinline__ void tf32_split(float x, unsigned &hi, unsigned &lo){
  unsigned hb = __float_as_uint(x) & 0xFFFFE000u;
  hi = hb;
  lo = __float_as_uint(x - __uint_as_float(hb));
}
// round-to-nearest tf32 (zero-mean rounding; stored value has low 13 bits zero,
// so feeding it straight to mma.tf32 is a no-op truncation)
__device__ __forceinline__ unsigned tf32_rna(float x){
  unsigned u; asm("cvt.rna.tf32.f32 %0, %1;" : "=r"(u) : "f"(x)); return u;
}
__device__ __forceinline__ float tf32_rnaf(float x){
  return __uint_as_float(tf32_rna(x));
}
__device__ __forceinline__ unsigned fu(float x){ return __float_as_uint(x); }

// ---------------- stage 0: weight transpose + split ----------------
__global__ void wsplit_kernel(const float* __restrict__ wqk,
                              const float* __restrict__ wv,
                              const float* __restrict__ wo){
  __shared__ float tile[32][33];
  int z = blockIdx.z;
  const float* src = (z==0) ? wqk : (z==1) ? wv : wo;
  float* dh = (z==0) ? g_wqkT_hi : (z==1) ? g_wvT_hi : g_woT_hi;
  float* dl = (z==0) ? g_wqkT_lo : (z==1) ? g_wvT_lo : g_woT_lo;
  int n0 = blockIdx.x*32, k0 = blockIdx.y*32;
  #pragma unroll
  for (int r=0;r<4;r++){
    int k = threadIdx.y + r*8;
    tile[k][threadIdx.x] = src[(k0+k)*EMBD + n0 + threadIdx.x];
  }
  __syncthreads();
  #pragma unroll
  for (int r=0;r<4;r++){
    int n = threadIdx.y + r*8;
    float v = tile[threadIdx.x][n];
    int oi = (n0+n)*EMBD + k0 + threadIdx.x;
    if (z == 2){
      dh[oi] = tf32_rnaf(v);
      dl[oi] = 0.f;
    } else {
      float hv = __uint_as_float(__float_as_uint(v) & 0xFFFFE000u);
      dh[oi] = hv;
      dl[oi] = v - hv;
    }
  }
}

// ---------------- stage 1: maxpool + Haar DWT -> tokens + accumulator zeroing ----------------
__global__ __launch_bounds__(256) void frontend_kernel(const float* __restrict__ x){
  __shared__ float s_x[32][33];
  int plane = blockIdx.x;            // b*128 + ch
  int b = plane >> 7, ch = plane & 127;
  const float* xp = x + (size_t)plane*1024;
  int t = threadIdx.x;

  // zero weighted-accumulation buffers (runs before attn each replay)
  {
    int gid = plane*256 + t;
    int total = BATCH*128*256;
    float4 z4 = make_float4(0.f,0.f,0.f,0.f);
    for (int i = gid; i < NROWS*EMBD/4; i += total)
      ((float4*)g_oacc)[i] = z4;
    if (gid < BHDIM*T) g_wsum[gid] = 0.f;
  }

  {
    float4 v = *(const float4*)(xp + t*4);
    int r = t >> 3, c4 = (t & 7)*4;
    s_x[r][c4]=v.x; s_x[r][c4+1]=v.y; s_x[r][c4+2]=v.z; s_x[r][c4+3]=v.w;
  }
  __syncthreads();

  int i = t >> 4, j = t & 15;
  float m = -INFINITY;
  int r0 = 2*i-1, c0 = 2*j-1;
  #pragma unroll
  for (int dr=0;dr<3;dr++){
    int r = r0+dr; if (r<0 || r>31) continue;
    #pragma unroll
    for (int dc=0;dc<3;dc++){
      int cc = c0+dc; if (cc<0 || cc>31) continue;
      m = fmaxf(m, s_x[r][cc]);
    }
  }
  float a  = s_x[2*i][2*j];
  float bb = s_x[2*i][2*j+1];
  float c  = s_x[2*i+1][2*j];
  float d  = s_x[2*i+1][2*j+1];
  float ll = (a+bb+c+d)*0.5f;
  float lh = (a-bb+c-d)*0.5f;
  float hl = (a+bb-c-d)*0.5f;
  float hh = (a-bb-c+d)*0.5f;

  size_t rowbase = (size_t)b*640;
  g_tokens[(rowbase + ch      )*256 + t] = m;
  g_tokens[(rowbase + 128 + ch)*256 + t] = ll;
  g_tokens[(rowbase + 256 + ch)*256 + t] = lh;
  g_tokens[(rowbase + 384 + ch)*256 + t] = hl;
  g_tokens[(rowbase + 512 + ch)*256 + t] = hh;
}

// ---------------- stage 2: fused qk/v GEMM, 3xTF32 tensor cores ----------------
#define SMEM_QKV ((128*36 + 4*64*36)*4)

__global__ __launch_bounds__(256) void gemm_qkv_tc(){
  extern __shared__ float sm[];
  float* s_a   = sm;                 // [128][36]
  float* s_b1h = s_a   + 128*36;     // [64][36]
  float* s_b1l = s_b1h + 64*36;
  float* s_b2h = s_b1l + 64*36;
  float* s_b2l = s_b2h + 64*36;

  int tid = threadIdx.x;
  int m0 = blockIdx.y*128, n0 = blockIdx.x*64;
  int warp = tid>>5, lane = tid&31;
  int g = lane>>2, tig = lane&3;
  int rA = warp*16 + g, rB = rA + 8;

  float acc1[8][4], acc2[8][4];
  #pragma unroll
  for (int nt=0;nt<8;nt++)
    #pragma unroll
    for (int u=0;u<4;u++){ acc1[nt][u]=0.f; acc2[nt][u]=0.f; }

  for (int kc=0;kc<EMBD;kc+=32){
    __syncthreads();
    {
      int row = tid>>1, half = (tid&1)*16;
      const float* asrc = g_tokens + (size_t)(m0+row)*EMBD + kc + half;
      #pragma unroll
      for (int u=0;u<16;u+=4)
        *(float4*)&s_a[row*36 + half + u] = *(const float4*)(asrc+u);
    }
    {
      int n = tid>>2, kq = (tid&3)*8;
      size_t bo = (size_t)(n0+n)*EMBD + kc + kq;
      *(float4*)&s_b1h[n*36+kq]   = *(const float4*)&g_wqkT_hi[bo];
      *(float4*)&s_b1h[n*36+kq+4] = *(const float4*)&g_wqkT_hi[bo+4];
      *(float4*)&s_b1l[n*36+kq]   = *(const float4*)&g_wqkT_lo[bo];
      *(float4*)&s_b1l[n*36+kq+4] = *(const float4*)&g_wqkT_lo[bo+4];
      *(float4*)&s_b2h[n*36+kq]   = *(const float4*)&g_wvT_hi[bo];
      *(float4*)&s_b2h[n*36+kq+4] = *(const float4*)&g_wvT_hi[bo+4];
      *(float4*)&s_b2l[n*36+kq]   = *(const float4*)&g_wvT_lo[bo];
      *(float4*)&s_b2l[n*36+kq+4] = *(const float4*)&g_wvT_lo[bo+4];
    }
    __syncthreads();

    #pragma unroll
    for (int kk=0;kk<32;kk+=8){
      unsigned ah[4], al[4];
      tf32_split(s_a[rA*36+kk+tig],   ah[0], al[0]);
      tf32_split(s_a[rB*36+kk+tig],   ah[1], al[1]);
      tf32_split(s_a[rA*36+kk+tig+4], ah[2], al[2]);
      tf32_split(s_a[rB*36+kk+tig+4], ah[3], al[3]);
      #pragma unroll
      for (int nt=0;nt<8;nt++){
        int nr = nt*8 + g;
        unsigned b1h[2] = { fu(s_b1h[nr*36+kk+tig]), fu(s_b1h[nr*36+kk+tig+4]) };
        unsigned b1l[2] = { fu(s_b1l[nr*36+kk+tig]), fu(s_b1l[nr*36+kk+tig+4]) };
        mma_tf32(acc1[nt], ah, b1h);
        mma_tf32(acc1[nt], al, b1h);
        mma_tf32(acc1[nt], ah, b1l);
        unsigned b2h[2] = { fu(s_b2h[nr*36+kk+tig]), fu(s_b2h[nr*36+kk+tig+4]) };
        unsigned b2l[2] = { fu(s_b2l[nr*36+kk+tig]), fu(s_b2l[nr*36+kk+tig+4]) };
        mma_tf32(acc2[nt], ah, b2h);
        mma_tf32(acc2[nt], al, b2h);
        mma_tf32(acc2[nt], ah, b2l);
      }
    }
  }
  int rowA = m0 + rA, rowB = m0 + rB;
  int bA = rowA/640, tokA = rowA - bA*640;
  int bB = rowB/640, tokB = rowB - bB*640;
  #pragma unroll
  for (int nt=0;nt<8;nt++){
    int col = n0 + nt*8 + 2*tig;
    int head = col>>5, dh = col&31;
    size_t oA = ((size_t)(bA*8+head)*640 + tokA)*32 + dh;
    size_t oB = ((size_t)(bB*8+head)*640 + tokB)*32 + dh;
    *(float2*)&g_qk[oA] = make_float2(acc1[nt][0], acc1[nt][1]);
    *(float2*)&g_v [oA] = make_float2(acc2[nt][0], acc2[nt][1]);
    *(float2*)&g_qk[oB] = make_float2(acc1[nt][2], acc1[nt][3]);
    *(float2*)&g_v [oB] = make_float2(acc2[nt][2], acc2[nt][3]);
  }
}

// ---------------- stage 3a: LSH bucket ids — warp-per-hash, 4 pos/thread ----------------
__global__ __launch_bounds__(256) void bucket_kernel(const float* __restrict__ rot){
  __shared__ float s_rot[1280];        // [f=32][h=8][i=5]
  __shared__ float s_q[128][33];
  int bh = blockIdx.x, pos0 = blockIdx.y*128;
  int tid = threadIdx.x;

  for (int i=tid;i<1280;i+=256) s_rot[i]=rot[i];
  {
    int row = tid>>1, fh = (tid&1)*16;
    const float* src = g_qk + ((size_t)bh*640 + pos0 + row)*32 + fh;
    #pragma unroll
    for (int u=0;u<16;u+=4){
      float4 v = *(const float4*)(src+u);
      s_q[row][fh+u]=v.x; s_q[row][fh+u+1]=v.y; s_q[row][fh+u+2]=v.z; s_q[row][fh+u+3]=v.w;
    }
  }
  __syncthreads();

  int h = tid>>5, l = tid&31;
  float r5[4][5];
  #pragma unroll
  for (int k=0;k<4;k++)
    #pragma unroll
    for (int i=0;i<5;i++) r5[k][i]=0.f;

  #pragma unroll 4
  for (int f=0;f<32;f++){
    const float* rp = s_rot + f*40 + h*5;   // warp-uniform -> broadcast
    float w0=rp[0], w1=rp[1], w2=rp[2], w3=rp[3], w4=rp[4];
    #pragma unroll
    for (int k=0;k<4;k++){
      float qf = s_q[l + 32*k][f];
      r5[k][0] += qf*w0; r5[k][1] += qf*w1; r5[k][2] += qf*w2;
      r5[k][3] += qf*w3; r5[k][4] += qf*w4;
    }
  }
  #pragma unroll
  for (int k=0;k<4;k++){
    float best = r5[k][0]; int bi = 0;
    #pragma unroll
    for (int i=1;i<5;i++) if (r5[k][i] > best){ best=r5[k][i]; bi=i; }
    #pragma unroll
    for (int i=0;i<5;i++){ float v = -r5[k][i]; if (v > best){ best=v; bi=5+i; } }
    g_bucket[(size_t)bh*NHASH*T + h*640 + pos0 + l + 32*k] = bi;
  }
}

// ---------------- stage 3b: stable counting sort per (bh, hash) — smem staged ----------------
__global__ __launch_bounds__(320) void sort_kernel(){
  __shared__ int s_bk[640];
  __shared__ int cnt[10], off[10];
  int bhh = blockIdx.x;
  const int* bk = g_bucket + bhh*640;
  for (int i=threadIdx.x;i<640;i+=320) s_bk[i]=bk[i];
  __syncthreads();

  int w = threadIdx.x>>5, lane = threadIdx.x&31;
  int count = 0;
  for (int base=0;base<640;base+=32){
    int bb = s_bk[base+lane];
    unsigned mask = __ballot_sync(0xffffffffu, bb==w);
    count += __popc(mask);
  }
  if (lane==0) cnt[w] = count;
  __syncthreads();
  if (threadIdx.x==0){
    int run=0;
    for (int b=0;b<10;b++){ off[b]=run; run+=cnt[b]; }
  }
  __syncthreads();
  int base_off = off[w]; int run = 0;
  int* out = g_sorted + bhh*640;
  for (int base=0;base<640;base+=32){
    int bb = s_bk[base+lane];
    unsigned mask = __ballot_sync(0xffffffffu, bb==w);
    if (bb==w){
      int slot = base_off + run + __popc(mask & ((1u<<lane)-1u));
      out[slot] = base+lane;
    }
    run += __popc(mask);
  }
}

// ---------------- stage 4: chunked attention, 1xTF32, fused weighted-combine epilogue ----------------
#define Q_PAD 36
#define K_PAD 36
#define V_PAD 40
#define P_PAD 132
#define SMEM_ATTN ((64*P_PAD + 128*V_PAD + 2*128)*4 + (64+128)*4)

__global__ __launch_bounds__(256) void attn_kernel(){
  extern __shared__ char smem_raw[];
  float* s_p    = (float*)smem_raw;          // [64][132]
  float* s_q    = s_p;                       // [64][36]  alias
  float* s_k    = s_p + 64*Q_PAD;            // [128][36] alias
  float* s_v    = s_p + 64*P_PAD;            // [128][40]
  float* s_redm = s_v + 128*V_PAD;           // [2][64]
  float* s_reds = s_redm + 128;              // [2][64]
  int*   s_qt   = (int*)(s_reds + 128);      // [64]
  int*   s_kt   = s_qt + 64;                 // [128]

  int tid = threadIdx.x;
  int blk = blockIdx.x;
  int bh = blk / NCHUNK, c = blk % NCHUNK;
  int h  = c / 10;
  int pc = (c + NCHUNK - 1) % NCHUNK;
  int ph = pc / 10;
  const int* sortedbh = g_sorted + bh*NHASH*T;

  if (tid < 64)
    s_qt[tid] = sortedbh[h*640 + (c%10)*64 + tid];
  else if (tid < 192){
    int j = tid - 64;
    s_kt[j] = (j < 64) ? sortedbh[h*640 + (c%10)*64 + j]
                       : sortedbh[ph*640 + (pc%10)*64 + (j-64)];
  }
  __syncthreads();

  // Q loader: pre-rna
  {
    int i = tid >> 2, f0 = (tid & 3) * 8;
    const float* src = g_qk + ((size_t)bh*640 + s_qt[i])*32 + f0;
    float4 a = *(const float4*)src;
    float4 b = *(const float4*)(src+4);
    s_q[i*Q_PAD+f0  ]=tf32_rnaf(a.x); s_q[i*Q_PAD+f0+1]=tf32_rnaf(a.y);
    s_q[i*Q_PAD+f0+2]=tf32_rnaf(a.z); s_q[i*Q_PAD+f0+3]=tf32_rnaf(a.w);
    s_q[i*Q_PAD+f0+4]=tf32_rnaf(b.x); s_q[i*Q_PAD+f0+5]=tf32_rnaf(b.y);
    s_q[i*Q_PAD+f0+6]=tf32_rnaf(b.z); s_q[i*Q_PAD+f0+7]=tf32_rnaf(b.w);
  }
  // K loader: normalize (exact fp32) then pre-rna
  {
    int j = tid >> 1, fh = (tid & 1) * 16;
    const float* src = g_qk + ((size_t)bh*640 + s_kt[j])*32 + fh;
    float buf[16]; float ss = 0.f;
    #pragma unroll
    for (int u=0;u<16;u+=4){
      float4 a = *(const float4*)(src+u);
      buf[u]=a.x; buf[u+1]=a.y; buf[u+2]=a.z; buf[u+3]=a.w;
      ss += a.x*a.x + a.y*a.y + a.z*a.z + a.w*a.w;
    }
    ss += __shfl_xor_sync(0xffffffffu, ss, 1);
    float inv = 1.f / fmaxf(sqrtf(ss), 1e-6f);
    #pragma unroll
    for (int u=0;u<16;u++)
      s_k[j*K_PAD + fh + u] = tf32_rnaf(buf[u]*inv);
  }
  // V loader: pre-rna
  {
    int j = tid >> 1, fh = (tid & 1) * 16;
    const float* src = g_v + ((size_t)bh*640 + s_kt[j])*32 + fh;
    #pragma unroll
    for (int u=0;u<16;u+=4){
      float4 a = *(const float4*)(src+u);
      s_v[j*V_PAD+fh+u  ]=tf32_rnaf(a.x); s_v[j*V_PAD+fh+u+1]=tf32_rnaf(a.y);
      s_v[j*V_PAD+fh+u+2]=tf32_rnaf(a.z); s_v[j*V_PAD+fh+u+3]=tf32_rnaf(a.w);
    }
  }
  __syncthreads();

  int warp = tid >> 5, lane = tid & 31;
  int wm = warp & 3, wn = warp >> 2;
  int g = lane >> 2, tig = lane & 3;
  int m0 = wm * 16;
  int rA = m0 + g, rB = m0 + g + 8;

  // ---- dots: 1xTF32, raw LDS ----
  float acc[8][4];
  #pragma unroll
  for (int nt=0;nt<8;nt++)
    #pragma unroll
    for (int u=0;u<4;u++) acc[nt][u] = 0.f;

  #pragma unroll
  for (int k0=0;k0<32;k0+=8){
    unsigned aq[4];
    aq[0] = fu(s_q[rA*Q_PAD + k0 + tig]);
    aq[1] = fu(s_q[rB*Q_PAD + k0 + tig]);
    aq[2] = fu(s_q[rA*Q_PAD + k0 + tig + 4]);
    aq[3] = fu(s_q[rB*Q_PAD + k0 + tig + 4]);
    #pragma unroll
    for (int nt=0;nt<8;nt++){
      int n0 = wn*64 + nt*8;
      unsigned bhh[2];
      bhh[0] = fu(s_k[(n0+g)*K_PAD + k0 + tig]);
      bhh[1] = fu(s_k[(n0+g)*K_PAD + k0 + tig + 4]);
      mma_tf32(acc[nt], aq, bhh);
    }
  }

  int qtA = s_qt[rA], qtB = s_qt[rB];
  #pragma unroll
  for (int nt=0;nt<8;nt++){
    int n0 = wn*64 + nt*8;
    int kt0 = s_kt[n0 + 2*tig], kt1 = s_kt[n0 + 2*tig + 1];
    acc[nt][0] = (kt0==qtA) ? -50000.f : acc[nt][0]*0.17677669529663687f;
    acc[nt][1] = (kt1==qtA) ? -50000.f : acc[nt][1]*0.17677669529663687f;
    acc[nt][2] = (kt0==qtB) ? -50000.f : acc[nt][2]*0.17677669529663687f;
    acc[nt][3] = (kt1==qtB) ? -50000.f : acc[nt][3]*0.17677669529663687f;
  }

  float mA=-INFINITY, mB=-INFINITY;
  #pragma unroll
  for (int nt=0;nt<8;nt++){
    mA = fmaxf(mA, fmaxf(acc[nt][0], acc[nt][1]));
    mB = fmaxf(mB, fmaxf(acc[nt][2], acc[nt][3]));
  }
  #pragma unroll
  for (int o=1;o<=2;o<<=1){
    mA = fmaxf(mA, __shfl_xor_sync(0xffffffffu, mA, o, 4));
    mB = fmaxf(mB, __shfl_xor_sync(0xffffffffu, mB, o, 4));
  }
  float sA=0.f, sB=0.f;
  #pragma unroll
  for (int nt=0;nt<8;nt++){
    acc[nt][0] = __expf(acc[nt][0]-mA);
    acc[nt][1] = __expf(acc[nt][1]-mA);
    acc[nt][2] = __expf(acc[nt][2]-mB);
    acc[nt][3] = __expf(acc[nt][3]-mB);
    sA += acc[nt][0] + acc[nt][1];
    sB += acc[nt][2] + acc[nt][3];
  }
  #pragma unroll
  for (int o=1;o<=2;o<<=1){
    sA += __shfl_xor_sync(0xffffffffu, sA, o, 4);
    sB += __shfl_xor_sync(0xffffffffu, sB, o, 4);
  }
  if (tig == 0){
    s_redm[wn*64 + rA] = mA;  s_reds[wn*64 + rA] = sA;
    s_redm[wn*64 + rB] = mB;  s_reds[wn*64 + rB] = sB;
  }
  __syncthreads();

  float lseA, lseB;
  {
    float m0A = s_redm[rA], m1A = s_redm[64+rA];
    float mm = fmaxf(m0A, m1A);
    float ss = s_reds[rA]*__expf(m0A-mm) + s_reds[64+rA]*__expf(m1A-mm);
    lseA = mm + __logf(ss);
    float m0B = s_redm[rB], m1B = s_redm[64+rB];
    mm = fmaxf(m0B, m1B);
    ss = s_reds[rB]*__expf(m0B-mm) + s_reds[64+rB]*__expf(m1B-mm);
    lseB = mm + __logf(ss);
  }
  // hash weight = exp(lse); accumulate into g_wsum (one thread per row)
  float wAe = __expf(lseA), wBe = __expf(lseB);
  if (wn == 0 && tig == 0){
    atomicAdd(&g_wsum[bh*640 + qtA], wAe);
    atomicAdd(&g_wsum[bh*640 + qtB], wBe);
  }

  // probs store: pre-rna
  float scA = __expf(mA - lseA);
  float scB = __expf(mB - lseB);
  #pragma unroll
  for (int nt=0;nt<8;nt++){
    int n0 = wn*64 + nt*8;
    *(float2*)&s_p[rA*P_PAD + n0 + 2*tig] =
      make_float2(tf32_rnaf(acc[nt][0]*scA), tf32_rnaf(acc[nt][1]*scA));
    *(float2*)&s_p[rB*P_PAD + n0 + 2*tig] =
      make_float2(tf32_rnaf(acc[nt][2]*scB), tf32_rnaf(acc[nt][3]*scB));
  }
  __syncthreads();

  // ---- PV: 1xTF32, raw LDS ----
  float o0[4] = {0.f,0.f,0.f,0.f};
  float o1[4] = {0.f,0.f,0.f,0.f};
  int d0 = wn*16;
  #pragma unroll 2
  for (int k0=0;k0<128;k0+=8){
    unsigned ap[4];
    ap[0] = fu(s_p[rA*P_PAD + k0 + tig]);
    ap[1] = fu(s_p[rB*P_PAD + k0 + tig]);
    ap[2] = fu(s_p[rA*P_PAD + k0 + tig + 4]);
    ap[3] = fu(s_p[rB*P_PAD + k0 + tig + 4]);
    unsigned b0h[2], b1h[2];
    b0h[0] = fu(s_v[(k0+tig)*V_PAD   + d0 + g]);
    b0h[1] = fu(s_v[(k0+tig+4)*V_PAD + d0 + g]);
    b1h[0] = fu(s_v[(k0+tig)*V_PAD   + d0 + 8 + g]);
    b1h[1] = fu(s_v[(k0+tig+4)*V_PAD + d0 + 8 + g]);
    mma_tf32(o0, ap, b0h);
    mma_tf32(o1, ap, b1h);
  }
  // fused combine: weighted atomic accumulation into merged-head layout
  {
    int b = bh >> 3, head = bh & 7;
    float* dA = g_oacc + ((size_t)(b*640 + qtA))*EMBD + head*32;
    float* dB = g_oacc + ((size_t)(b*640 + qtB))*EMBD + head*32;
    atomicAdd(dA + d0 + 2*tig,     o0[0]*wAe);
    atomicAdd(dA + d0 + 2*tig + 1, o0[1]*wAe);
    atomicAdd(dB + d0 + 2*tig,     o0[2]*wBe);
    atomicAdd(dB + d0 + 2*tig + 1, o0[3]*wBe);
    atomicAdd(dA + d0 + 8 + 2*tig,     o1[0]*wAe);
    atomicAdd(dA + d0 + 8 + 2*tig + 1, o1[1]*wAe);
    atomicAdd(dB + d0 + 8 + 2*tig,     o1[2]*wBe);
    atomicAdd(dB + d0 + 8 + 2*tig + 1, o1[3]*wBe);
  }
}

// ---------------- stage 6: output GEMM + bias, 2xTF32, normalize-in-loader ----------------
__global__ __launch_bounds__(256) void gemm_out_tc(const float* __restrict__ bias,
                                                   float* __restrict__ out){
  __shared__ float s_a[128*36];
  __shared__ float s_bh[64*36];

  int tid = threadIdx.x;
  int m0 = blockIdx.y*128, n0 = blockIdx.x*64;
  int warp = tid>>5, lane = tid&31;
  int g = lane>>2, tig = lane&3;
  int rA = warp*16 + g, rB = rA + 8;

  float acc[8][4];
  #pragma unroll
  for (int nt=0;nt<8;nt++)
    #pragma unroll
    for (int u=0;u<4;u++) acc[nt][u]=0.f;

  for (int kc=0;kc<EMBD;kc+=32){
    __syncthreads();
    {
      int row = tid>>1, half = (tid&1)*16;
      int grow = m0 + row;
      int b = grow/640, pos = grow - b*640;
      int head = (kc + half) >> 5;           // 16-float span stays in one head
      float inv = 1.f / g_wsum[(b*8+head)*640 + pos];
      const float* asrc = g_oacc + (size_t)grow*EMBD + kc + half;
      #pragma unroll
      for (int u=0;u<16;u+=4){
        float4 a = *(const float4*)(asrc+u);
        *(float4*)&s_a[row*36 + half + u] =
          make_float4(a.x*inv, a.y*inv, a.z*inv, a.w*inv);
      }
    }
    {
      int n = tid>>2, kq = (tid&3)*8;
      size_t bo = (size_t)(n0+n)*EMBD + kc + kq;
      *(float4*)&s_bh[n*36+kq]   = *(const float4*)&g_woT_hi[bo];
      *(float4*)&s_bh[n*36+kq+4] = *(const float4*)&g_woT_hi[bo+4];
    }
    __syncthreads();

    #pragma unroll
    for (int kk=0;kk<32;kk+=8){
      unsigned ah[4], al[4];
      tf32_split(s_a[rA*36+kk+tig],   ah[0], al[0]);
      tf32_split(s_a[rB*36+kk+tig],   ah[1], al[1]);
      tf32_split(s_a[rA*36+kk+tig+4], ah[2], al[2]);
      tf32_split(s_a[rB*36+kk+tig+4], ah[3], al[3]);
      #pragma unroll
      for (int nt=0;nt<8;nt++){
        int nr = nt*8 + g;
        unsigned bhv[2] = { fu(s_bh[nr*36+kk+tig]), fu(s_bh[nr*36+kk+tig+4]) };
        mma_tf32(acc[nt], ah, bhv);
        mma_tf32(acc[nt], al, bhv);
      }
    }
  }
  int rowA = m0 + rA, rowB = m0 + rB;
  #pragma unroll
  for (int nt=0;nt<8;nt++){
    int col = n0 + nt*8 + 2*tig;
    float b0 = __ldg(bias+col), b1 = __ldg(bias+col+1);
    *(float2*)&out[(size_t)rowA*EMBD + col] = make_float2(acc[nt][0]+b0, acc[nt][1]+b1);
    *(float2*)&out[(size_t)rowB*EMBD + col] = make_float2(acc[nt][2]+b0, acc[nt][3]+b1);
  }
}

// ---------------- launch ----------------
extern "C" void kernel_launch(void* const* d_in, const int* in_sizes, int n_in,
                              void* d_out, int out_size){
  const float* x     = (const float*)d_in[0];
  const float* w_qk  = (const float*)d_in[1];
  const float* w_v   = (const float*)d_in[2];
  const float* w_out = (const float*)d_in[3];
  const float* b_out = (const float*)d_in[4];
  const float* rot   = (const float*)d_in[5];
  float* out = (float*)d_out;

  wsplit_kernel<<<dim3(8,8,3), dim3(32,8)>>>(w_qk, w_v, w_out);
  frontend_kernel<<<BATCH*128, 256>>>(x);
  cudaFuncSetAttribute(gemm_qkv_tc, cudaFuncAttributeMaxDynamicSharedMemorySize, SMEM_QKV);
  gemm_qkv_tc<<<dim3(4,80), 256, SMEM_QKV>>>();
  bucket_kernel<<<dim3(BHDIM, T/128), 256>>>(rot);
  sort_kernel<<<BHDIM*NHASH, 320>>>();
  cudaFuncSetAttribute(attn_kernel, cudaFuncAttributeMaxDynamicSharedMemorySize, SMEM_ATTN);
  attn_kernel<<<BHDIM*NCHUNK, 256, SMEM_ATTN>>>();
  gemm_out_tc<<<dim3(4,80), 256>>>(b_out, out);
}